// round 2
// baseline (speedup 1.0000x reference)
#include <cuda_runtime.h>
#include <math_constants.h>
#include <stdint.h>

// Shapes (fixed for this problem)
#define L1S 512
#define L2S 512
#define BSZ 32
#define DIM 1024
#define MROWS (L1S * BSZ)   // 16384

// Scratch (device globals: allocation-free rule)
__device__ float g_T[(size_t)MROWS * DIM];              // 64 MB: H1_flat @ W
__device__ float g_S[(size_t)BSZ * L1S * L2S];          // 32 MB: scores
__device__ unsigned char g_valid1[MROWS];
__device__ unsigned char g_valid2[L2S * BSZ];
__device__ int g_is32;

// ---------------------------------------------------------------------------
// Mask dtype detection: int32 data viewed as int64 must contain a value > 1
// somewhere in the first 8192 words (16384 random 0/1s); genuine int64 data
// contains only {0,1}.
// ---------------------------------------------------------------------------
__global__ void detect_kernel(const unsigned long long* __restrict__ m1) {
    __shared__ int s;
    if (threadIdx.x == 0) s = 0;
    __syncthreads();
    int bad = 0;
    for (int i = threadIdx.x; i < 8192; i += blockDim.x)
        if (m1[i] > 1ULL) bad = 1;
    if (bad) atomicOr(&s, 1);
    __syncthreads();
    if (threadIdx.x == 0) g_is32 = s;
}

__global__ void convert_kernel(const void* __restrict__ m1, const void* __restrict__ m2) {
    int i = blockIdx.x * blockDim.x + threadIdx.x;
    if (i >= MROWS) return;
    bool is32 = (g_is32 != 0);
    long long v1 = is32 ? (long long)((const int*)m1)[i] : ((const long long*)m1)[i];
    long long v2 = is32 ? (long long)((const int*)m2)[i] : ((const long long*)m2)[i];
    g_valid1[i] = (v1 == 0);
    g_valid2[i] = (v2 == 0);
}

// ---------------------------------------------------------------------------
// GEMM1: g_T[M=16384, N=1024] = A[M, K=1024] (row-major) * W[K, N] (row-major)
// 128x128 block tile, BK=8, 256 threads, 8x8 per thread.
// ---------------------------------------------------------------------------
__global__ void __launch_bounds__(256) gemm1_kernel(
    const float* __restrict__ A, const float* __restrict__ W, float* __restrict__ C) {
    const int N = DIM, K = DIM;
    __shared__ float As[8][128];
    __shared__ float Bs[8][128];
    int tid = threadIdx.x;
    int rowBlock = blockIdx.y * 128;
    int colBlock = blockIdx.x * 128;
    int tx = tid & 15, ty = tid >> 4;

    float acc[8][8];
    #pragma unroll
    for (int i = 0; i < 8; i++)
        #pragma unroll
        for (int j = 0; j < 8; j++) acc[i][j] = 0.0f;

    int aRow = tid >> 1;
    int aCol4 = (tid & 1) * 4;
    int bRow = tid >> 5;
    int bCol4 = (tid & 31) * 4;

    const float* aPtr = A + (size_t)(rowBlock + aRow) * K + aCol4;
    const float* bPtr = W + (size_t)bRow * N + colBlock + bCol4;

    for (int kt = 0; kt < K; kt += 8) {
        float4 av = *(const float4*)(aPtr + kt);
        float4 bv = *(const float4*)(bPtr + (size_t)kt * N);
        As[aCol4 + 0][aRow] = av.x; As[aCol4 + 1][aRow] = av.y;
        As[aCol4 + 2][aRow] = av.z; As[aCol4 + 3][aRow] = av.w;
        *(float4*)&Bs[bRow][bCol4] = bv;
        __syncthreads();
        #pragma unroll
        for (int k = 0; k < 8; k++) {
            float ar[8], br[8];
            #pragma unroll
            for (int i = 0; i < 8; i++) ar[i] = As[k][ty * 8 + i];
            #pragma unroll
            for (int j = 0; j < 8; j++) br[j] = Bs[k][tx * 8 + j];
            #pragma unroll
            for (int i = 0; i < 8; i++)
                #pragma unroll
                for (int j = 0; j < 8; j++)
                    acc[i][j] = fmaf(ar[i], br[j], acc[i][j]);
        }
        __syncthreads();
    }

    #pragma unroll
    for (int i = 0; i < 8; i++) {
        int r = rowBlock + ty * 8 + i;
        #pragma unroll
        for (int j = 0; j < 8; j += 4) {
            float4 v = make_float4(acc[i][j], acc[i][j+1], acc[i][j+2], acc[i][j+3]);
            *(float4*)(C + (size_t)r * N + colBlock + tx * 8 + j) = v;
        }
    }
}

// ---------------------------------------------------------------------------
// GEMM2 (batched NT): S_b[512,512] = T_b[512,1024] * H2_b^T, +bias, relu, mask
// T_b row i lives at g_T + (i*BSZ + b)*DIM; H2_b row j at H2 + (j*BSZ + b)*DIM.
// ---------------------------------------------------------------------------
__global__ void __launch_bounds__(256) gemm2_kernel(
    const float* __restrict__ T, const float* __restrict__ H2,
    const unsigned char* __restrict__ v1, const unsigned char* __restrict__ v2,
    const float* __restrict__ bias, float* __restrict__ S) {
    const int D = DIM, L = L2S;
    int bat = blockIdx.z;
    int rowBlock = blockIdx.y * 128;
    int colBlock = blockIdx.x * 128;
    __shared__ float As[8][128];
    __shared__ float Bs[8][128];
    int tid = threadIdx.x;
    int tx = tid & 15, ty = tid >> 4;
    int aRow = tid >> 1;
    int aCol4 = (tid & 1) * 4;

    float acc[8][8];
    #pragma unroll
    for (int i = 0; i < 8; i++)
        #pragma unroll
        for (int j = 0; j < 8; j++) acc[i][j] = 0.0f;

    const float* aPtr = T  + ((size_t)(rowBlock + aRow) * BSZ + bat) * D + aCol4;
    const float* bPtr = H2 + ((size_t)(colBlock + aRow) * BSZ + bat) * D + aCol4;

    for (int kt = 0; kt < D; kt += 8) {
        float4 av = *(const float4*)(aPtr + kt);
        float4 bv = *(const float4*)(bPtr + kt);
        As[aCol4 + 0][aRow] = av.x; As[aCol4 + 1][aRow] = av.y;
        As[aCol4 + 2][aRow] = av.z; As[aCol4 + 3][aRow] = av.w;
        Bs[aCol4 + 0][aRow] = bv.x; Bs[aCol4 + 1][aRow] = bv.y;
        Bs[aCol4 + 2][aRow] = bv.z; Bs[aCol4 + 3][aRow] = bv.w;
        __syncthreads();
        #pragma unroll
        for (int k = 0; k < 8; k++) {
            float ar[8], br[8];
            #pragma unroll
            for (int i = 0; i < 8; i++) ar[i] = As[k][ty * 8 + i];
            #pragma unroll
            for (int j = 0; j < 8; j++) br[j] = Bs[k][tx * 8 + j];
            #pragma unroll
            for (int i = 0; i < 8; i++)
                #pragma unroll
                for (int j = 0; j < 8; j++)
                    acc[i][j] = fmaf(ar[i], br[j], acc[i][j]);
        }
        __syncthreads();
    }

    float bb = bias[0];
    #pragma unroll
    for (int i = 0; i < 8; i++) {
        int r = rowBlock + ty * 8 + i;
        bool ok1 = v1[r * BSZ + bat];
        #pragma unroll
        for (int j = 0; j < 8; j++) {
            int c = colBlock + tx * 8 + j;
            float v = fmaxf(acc[i][j] + bb, 0.0f);
            if (!ok1 || !v2[c * BSZ + bat]) v = -CUDART_INF_F;
            S[((size_t)bat * L1S + r) * L + c] = v;
        }
    }
}

// ---------------------------------------------------------------------------
// Top-k per batch. One block per batch. Histogram positive values only
// (relu => candidates for top-k are positive except in degenerate cases).
// Bucket = float bits >> 20 (monotonic for positive floats, 2048 buckets).
// ---------------------------------------------------------------------------
#define NB 2048
#define CAP 4096

__global__ void __launch_bounds__(256) topk_kernel(
    const float* __restrict__ S, float* __restrict__ out, int kk) {
    int bat = blockIdx.x;
    const int NE = L1S * L2S;
    const float* Sb = S + (size_t)bat * NE;

    __shared__ int hist[NB];
    __shared__ float cand[CAP];
    __shared__ int chunkS[128];
    __shared__ int validArr[256];
    __shared__ int s_cnt, s_cutoff, s_nPos, s_nValid;

    int tid = threadIdx.x;
    for (int i = tid; i < NB; i += 256) hist[i] = 0;
    if (tid == 0) s_cnt = 0;
    __syncthreads();

    int myValid = 0;
    for (int t = tid; t < NE; t += 256) {
        float f = Sb[t];
        if (f >= 0.0f) myValid++;           // valid entries (invalid == -inf)
        if (f > 0.0f) {
            unsigned u = __float_as_uint(f);
            atomicAdd(&hist[u >> 20], 1);
        }
    }
    validArr[tid] = myValid;
    __syncthreads();
    for (int s = 128; s > 0; s >>= 1) {
        if (tid < s) validArr[tid] += validArr[tid + s];
        __syncthreads();
    }
    if (tid < 128) {
        int s = 0;
        #pragma unroll
        for (int b = 0; b < 16; b++) s += hist[tid * 16 + b];
        chunkS[tid] = s;
    }
    __syncthreads();

    if (tid == 0) {
        int acc = 0, c = -1;
        for (int ch = 127; ch >= 0 && c < 0; ch--) {
            if (acc + chunkS[ch] >= kk) {
                for (int b = ch * 16 + 15; b >= ch * 16; b--) {
                    acc += hist[b];
                    if (acc >= kk) { c = b; break; }
                }
            } else acc += chunkS[ch];
        }
        int totalPos = 0;
        for (int ch = 0; ch < 128; ch++) totalPos += chunkS[ch];
        if (c < 0) c = 0;  // fewer than kk positives: take all positives
        s_cutoff = c;
        s_nPos = totalPos;
        s_nValid = validArr[0];
    }
    __syncthreads();

    unsigned c = (unsigned)s_cutoff;
    for (int t = tid; t < NE; t += 256) {
        float f = Sb[t];
        if (f > 0.0f && (__float_as_uint(f) >> 20) >= c) {
            int idx = atomicAdd(&s_cnt, 1);
            if (idx < CAP) cand[idx] = f;
        }
    }
    __syncthreads();

    int m = min(s_cnt, CAP);
    int P = 2;
    while (P < m) P <<= 1;
    for (int i = m + tid; i < P; i += 256) cand[i] = -1.0f;
    __syncthreads();

    // bitonic sort, descending
    for (int size = 2; size <= P; size <<= 1) {
        for (int stride = size >> 1; stride > 0; stride >>= 1) {
            for (int j = tid; j < P; j += 256) {
                int p = j ^ stride;
                if (p > j) {
                    bool down = ((j & size) == 0);
                    float a = cand[j], b = cand[p];
                    if (down ? (a < b) : (a > b)) { cand[j] = b; cand[p] = a; }
                }
            }
            __syncthreads();
        }
    }

    int nPos = s_nPos, nValid = s_nValid;
    int nc = min(min(nPos, m), kk);  // usable sorted positive candidates
    for (int pos = tid; pos < kk; pos += 256) {
        float v;
        if (pos < nc) v = cand[pos];
        else if (pos < nValid) v = 0.0f;      // remaining valid entries are relu-zeros
        else {
            // -inf tail: fill with last finite value of the row
            int lastIdx = min(nValid, kk);
            if (lastIdx > nc) v = 0.0f;
            else v = (nc > 0) ? cand[nc - 1] : 0.0f;
        }
        out[(size_t)bat * kk + pos] = v;
    }
}

// ---------------------------------------------------------------------------
extern "C" void kernel_launch(void* const* d_in, const int* in_sizes, int n_in,
                              void* d_out, int out_size) {
    const float* inputs1 = (const float*)d_in[0];
    const float* inputs2 = (const float*)d_in[1];
    const void*  mask1   = d_in[2];
    const void*  mask2   = d_in[3];
    const float* W       = (const float*)d_in[4];
    const float* bias    = (const float*)d_in[5];
    int kk = out_size / BSZ;   // 256

    float* T;  cudaGetSymbolAddress((void**)&T,  g_T);
    float* S;  cudaGetSymbolAddress((void**)&S,  g_S);
    unsigned char* v1; cudaGetSymbolAddress((void**)&v1, g_valid1);
    unsigned char* v2; cudaGetSymbolAddress((void**)&v2, g_valid2);

    detect_kernel<<<1, 256>>>((const unsigned long long*)mask1);
    convert_kernel<<<(MROWS + 255) / 256, 256>>>(mask1, mask2);

    dim3 g1(DIM / 128, MROWS / 128);       // (8, 128)
    gemm1_kernel<<<g1, 256>>>(inputs1, W, T);

    dim3 g2(L2S / 128, L1S / 128, BSZ);    // (4, 4, 32)
    gemm2_kernel<<<g2, 256>>>(T, inputs2, v1, v2, bias, S);

    topk_kernel<<<BSZ, 256>>>(S, (float*)d_out, kk);
}

// round 5
// speedup vs baseline: 1.6116x; 1.6116x over previous
#include <cuda_runtime.h>
#include <cuda_bf16.h>
#include <math_constants.h>
#include <stdint.h>

typedef __nv_bfloat16 bf16;

#define L1S 512
#define L2S 512
#define BSZ 32
#define DIM 1024
#define MROWS (L1S * BSZ)   // 16384

#define BM 128
#define BN 128
#define BK 16
#define NTHREADS 256

// ------------------------- device global scratch ---------------------------
__device__ bf16 g_A1h[(size_t)MROWS * DIM];
__device__ bf16 g_A1l[(size_t)MROWS * DIM];
__device__ bf16 g_H2h[(size_t)MROWS * DIM];
__device__ bf16 g_H2l[(size_t)MROWS * DIM];
__device__ bf16 g_Th [(size_t)MROWS * DIM];
__device__ bf16 g_Tl [(size_t)MROWS * DIM];
__device__ bf16 g_Wth[(size_t)DIM * DIM];
__device__ bf16 g_Wtl[(size_t)DIM * DIM];
__device__ float g_S[(size_t)BSZ * L1S * L2S];
__device__ unsigned char g_valid1[MROWS];
__device__ unsigned char g_valid2[L2S * BSZ];
__device__ int g_is32;

// ------------------------- mask dtype detect + convert ---------------------
__global__ void detect_kernel(const unsigned long long* __restrict__ m1) {
    __shared__ int s;
    if (threadIdx.x == 0) s = 0;
    __syncthreads();
    int bad = 0;
    for (int i = threadIdx.x; i < 8192; i += blockDim.x)
        if (m1[i] > 1ULL) bad = 1;
    if (bad) atomicOr(&s, 1);
    __syncthreads();
    if (threadIdx.x == 0) g_is32 = s;
}

__global__ void convert_kernel(const void* __restrict__ m1, const void* __restrict__ m2) {
    int i = blockIdx.x * blockDim.x + threadIdx.x;
    if (i >= MROWS) return;
    bool is32 = (g_is32 != 0);
    long long v1 = is32 ? (long long)((const int*)m1)[i] : ((const long long*)m1)[i];
    long long v2 = is32 ? (long long)((const int*)m2)[i] : ((const long long*)m2)[i];
    g_valid1[i] = (v1 == 0);
    g_valid2[i] = (v2 == 0);
}

// ------------------------- fp32 -> bf16 hi/lo split ------------------------
__device__ __forceinline__ void split1(float v, bf16& h, bf16& l) {
    h = __float2bfloat16(v);
    l = __float2bfloat16(v - __bfloat162float(h));
}

__global__ void __launch_bounds__(256) split_kernel(
    const float4* __restrict__ in, __nv_bfloat162* __restrict__ hi,
    __nv_bfloat162* __restrict__ lo, int n4) {
    int i = blockIdx.x * blockDim.x + threadIdx.x;
    if (i >= n4) return;
    float4 v = in[i];
    __nv_bfloat162 h0, h1, l0, l1;
    split1(v.x, h0.x, l0.x); split1(v.y, h0.y, l0.y);
    split1(v.z, h1.x, l1.x); split1(v.w, h1.y, l1.y);
    hi[i * 2] = h0; hi[i * 2 + 1] = h1;
    lo[i * 2] = l0; lo[i * 2 + 1] = l1;
}

// transpose + split W[k][n] -> Wt[n][k] hi/lo
__global__ void splitT_kernel(const float* __restrict__ W,
                              bf16* __restrict__ Wth, bf16* __restrict__ Wtl) {
    __shared__ float tile[32][33];
    int k0 = blockIdx.y * 32, n0 = blockIdx.x * 32;
    for (int r = threadIdx.y; r < 32; r += 8)
        tile[r][threadIdx.x] = W[(size_t)(k0 + r) * DIM + n0 + threadIdx.x];
    __syncthreads();
    for (int r = threadIdx.y; r < 32; r += 8) {
        float v = tile[threadIdx.x][r];
        bf16 h, l; split1(v, h, l);
        size_t o = (size_t)(n0 + r) * DIM + k0 + threadIdx.x;
        Wth[o] = h; Wtl[o] = l;
    }
}

// ------------------------- tensor-core GEMM core ---------------------------
__device__ __forceinline__ void cp16(void* dst, const void* src) {
    unsigned d = (unsigned)__cvta_generic_to_shared(dst);
    asm volatile("cp.async.cg.shared.global [%0], [%1], 16;\n" :: "r"(d), "l"(src));
}

__device__ __forceinline__ void mma16816(float* c, const unsigned* a, const unsigned* b) {
    asm volatile(
        "mma.sync.aligned.m16n8k16.row.col.f32.bf16.bf16.f32 "
        "{%0,%1,%2,%3}, {%4,%5,%6,%7}, {%8,%9}, {%0,%1,%2,%3};\n"
        : "+f"(c[0]), "+f"(c[1]), "+f"(c[2]), "+f"(c[3])
        : "r"(a[0]), "r"(a[1]), "r"(a[2]), "r"(a[3]), "r"(b[0]), "r"(b[1]));
}

// C[BM,BN] += A[BM,K] * B[BN,K]^T with bf16x3 splits. Row strides in elements.
// Warp layout: 8 warps = 2(m) x 4(n); warp tile 64x32.
__device__ __forceinline__ void gemm_core(
    const bf16* __restrict__ pAh, const bf16* __restrict__ pAl, size_t ldA,
    const bf16* __restrict__ pBh, const bf16* __restrict__ pBl, size_t ldB,
    int K, float acc[4][4][4]) {

    __shared__ __align__(16) bf16 sA[2][2][BM * 24];   // [stage][hi/lo]
    __shared__ __align__(16) bf16 sB[2][2][BN * 24];

    const int tid = threadIdx.x;
    const int lane = tid & 31, warp = tid >> 5;
    const int wm = warp >> 2, wn = warp & 3;
    const int WR = wm * 64, WC = wn * 32;
    const int g = lane >> 2, t = lane & 3;

    #pragma unroll
    for (int a = 0; a < 4; a++)
        #pragma unroll
        for (int b = 0; b < 4; b++)
            #pragma unroll
            for (int c = 0; c < 4; c++) acc[a][b][c] = 0.0f;

    auto issue = [&](int kt, int buf) {
        #pragma unroll
        for (int j = 0; j < 4; j++) {
            int cid = tid + j * 256;
            int arr = cid >> 8;
            int rc = cid & 255;
            int row = rc >> 1, ch = rc & 1;
            int soff = row * 24 + ch * 8;
            int goff = kt + ch * 8;
            if (arr == 0)      cp16(&sA[buf][0][soff], pAh + (size_t)row * ldA + goff);
            else if (arr == 1) cp16(&sA[buf][1][soff], pAl + (size_t)row * ldA + goff);
            else if (arr == 2) cp16(&sB[buf][0][soff], pBh + (size_t)row * ldB + goff);
            else               cp16(&sB[buf][1][soff], pBl + (size_t)row * ldB + goff);
        }
        asm volatile("cp.async.commit_group;\n" ::);
    };

    const int NK = K >> 4;
    issue(0, 0);

    for (int i = 0; i < NK; i++) {
        int buf = i & 1;
        asm volatile("cp.async.wait_group 0;\n" ::);
        __syncthreads();
        if (i + 1 < NK) issue((i + 1) << 4, (i + 1) & 1);

        const unsigned* Ah = (const unsigned*)sA[buf][0];
        const unsigned* Al = (const unsigned*)sA[buf][1];
        const unsigned* Bh = (const unsigned*)sB[buf][0];
        const unsigned* Bl = (const unsigned*)sB[buf][1];

        unsigned bh[4][2], bl[4][2];
        #pragma unroll
        for (int nt = 0; nt < 4; nt++) {
            int n = (WC + nt * 8 + g) * 12;
            bh[nt][0] = Bh[n + t];     bh[nt][1] = Bh[n + 4 + t];
            bl[nt][0] = Bl[n + t];     bl[nt][1] = Bl[n + 4 + t];
        }
        #pragma unroll
        for (int mt = 0; mt < 4; mt++) {
            int r0 = (WR + mt * 16 + g) * 12;
            int r1 = r0 + 8 * 12;
            unsigned ah[4] = {Ah[r0 + t], Ah[r1 + t], Ah[r0 + 4 + t], Ah[r1 + 4 + t]};
            unsigned al[4] = {Al[r0 + t], Al[r1 + t], Al[r0 + 4 + t], Al[r1 + 4 + t]};
            #pragma unroll
            for (int nt = 0; nt < 4; nt++) {
                mma16816(acc[mt][nt], ah, bh[nt]);
                mma16816(acc[mt][nt], ah, bl[nt]);
                mma16816(acc[mt][nt], al, bh[nt]);
            }
        }
        __syncthreads();
    }
}

// GEMM1: T = A1[16384,1024] * Wt[1024,1024]^T, epilogue splits to bf16 hi/lo
__global__ void __launch_bounds__(NTHREADS, 1) gemm1_kernel(
    const bf16* __restrict__ Ah, const bf16* __restrict__ Al,
    const bf16* __restrict__ Bh, const bf16* __restrict__ Bl,
    bf16* __restrict__ Th, bf16* __restrict__ Tl) {

    float acc[4][4][4];
    gemm_core(Ah + (size_t)blockIdx.y * BM * DIM, Al + (size_t)blockIdx.y * BM * DIM, DIM,
              Bh + (size_t)blockIdx.x * BN * DIM, Bl + (size_t)blockIdx.x * BN * DIM, DIM,
              DIM, acc);

    const int lane = threadIdx.x & 31, warp = threadIdx.x >> 5;
    const int g = lane >> 2, t = lane & 3;
    const int gR = blockIdx.y * BM + (warp >> 2) * 64;
    const int gC = blockIdx.x * BN + (warp & 3) * 32;

    #pragma unroll
    for (int mt = 0; mt < 4; mt++) {
        int r0 = gR + mt * 16 + g;
        #pragma unroll
        for (int nt = 0; nt < 4; nt++) {
            int c0 = gC + nt * 8 + t * 2;
            __nv_bfloat162 h, l;
            split1(acc[mt][nt][0], h.x, l.x);
            split1(acc[mt][nt][1], h.y, l.y);
            *(__nv_bfloat162*)(Th + (size_t)r0 * DIM + c0) = h;
            *(__nv_bfloat162*)(Tl + (size_t)r0 * DIM + c0) = l;
            split1(acc[mt][nt][2], h.x, l.x);
            split1(acc[mt][nt][3], h.y, l.y);
            *(__nv_bfloat162*)(Th + (size_t)(r0 + 8) * DIM + c0) = h;
            *(__nv_bfloat162*)(Tl + (size_t)(r0 + 8) * DIM + c0) = l;
        }
    }
}

// GEMM2 (batched NT): S_b = T_b * H2_b^T + bias, relu, mask
__global__ void __launch_bounds__(NTHREADS, 1) gemm2_kernel(
    const bf16* __restrict__ Th, const bf16* __restrict__ Tl,
    const bf16* __restrict__ Hh, const bf16* __restrict__ Hl,
    const unsigned char* __restrict__ v1, const unsigned char* __restrict__ v2,
    const float* __restrict__ bias, float* __restrict__ S) {

    const int bat = blockIdx.z;
    const size_t ld = (size_t)BSZ * DIM;
    float acc[4][4][4];
    gemm_core(Th + (size_t)bat * DIM + (size_t)blockIdx.y * BM * ld,
              Tl + (size_t)bat * DIM + (size_t)blockIdx.y * BM * ld, ld,
              Hh + (size_t)bat * DIM + (size_t)blockIdx.x * BN * ld,
              Hl + (size_t)bat * DIM + (size_t)blockIdx.x * BN * ld, ld,
              DIM, acc);

    const int lane = threadIdx.x & 31, warp = threadIdx.x >> 5;
    const int g = lane >> 2, t = lane & 3;
    const int gR = blockIdx.y * BM + (warp >> 2) * 64;
    const int gC = blockIdx.x * BN + (warp & 3) * 32;
    const float bb = bias[0];

    #pragma unroll
    for (int mt = 0; mt < 4; mt++) {
        #pragma unroll
        for (int rr = 0; rr < 2; rr++) {
            int r = gR + mt * 16 + g + rr * 8;
            bool okR = v1[r * BSZ + bat];
            #pragma unroll
            for (int nt = 0; nt < 4; nt++) {
                int c = gC + nt * 8 + t * 2;
                float va = acc[mt][nt][rr * 2 + 0];
                float vb = acc[mt][nt][rr * 2 + 1];
                va = fmaxf(va + bb, 0.0f);
                vb = fmaxf(vb + bb, 0.0f);
                if (!okR || !v2[c * BSZ + bat])       va = -CUDART_INF_F;
                if (!okR || !v2[(c + 1) * BSZ + bat]) vb = -CUDART_INF_F;
                float2 o = make_float2(va, vb);
                *(float2*)(S + ((size_t)bat * L1S + r) * L2S + c) = o;
            }
        }
    }
}

// ------------------------- top-k per batch ---------------------------------
#define NB 2048
#define CAP 4096

__global__ void __launch_bounds__(256) topk_kernel(
    const float* __restrict__ S, float* __restrict__ out, int kk) {
    int bat = blockIdx.x;
    const int NE = L1S * L2S;
    const float* Sb = S + (size_t)bat * NE;

    __shared__ int hist[NB];
    __shared__ float cand[CAP];
    __shared__ int chunkS[128];
    __shared__ int validArr[256];
    __shared__ int s_cnt, s_cutoff, s_nPos, s_nValid;

    int tid = threadIdx.x;
    for (int i = tid; i < NB; i += 256) hist[i] = 0;
    if (tid == 0) s_cnt = 0;
    __syncthreads();

    int myValid = 0;
    for (int t = tid; t < NE; t += 256) {
        float f = Sb[t];
        if (f >= 0.0f) myValid++;
        if (f > 0.0f) {
            unsigned u = __float_as_uint(f);
            atomicAdd(&hist[u >> 20], 1);
        }
    }
    validArr[tid] = myValid;
    __syncthreads();
    for (int s = 128; s > 0; s >>= 1) {
        if (tid < s) validArr[tid] += validArr[tid + s];
        __syncthreads();
    }
    if (tid < 128) {
        int s = 0;
        #pragma unroll
        for (int b = 0; b < 16; b++) s += hist[tid * 16 + b];
        chunkS[tid] = s;
    }
    __syncthreads();

    if (tid == 0) {
        int acc = 0, c = -1;
        for (int ch = 127; ch >= 0 && c < 0; ch--) {
            if (acc + chunkS[ch] >= kk) {
                for (int b = ch * 16 + 15; b >= ch * 16; b--) {
                    acc += hist[b];
                    if (acc >= kk) { c = b; break; }
                }
            } else acc += chunkS[ch];
        }
        int totalPos = 0;
        for (int ch = 0; ch < 128; ch++) totalPos += chunkS[ch];
        if (c < 0) c = 0;
        s_cutoff = c;
        s_nPos = totalPos;
        s_nValid = validArr[0];
    }
    __syncthreads();

    unsigned c = (unsigned)s_cutoff;
    for (int t = tid; t < NE; t += 256) {
        float f = Sb[t];
        if (f > 0.0f && (__float_as_uint(f) >> 20) >= c) {
            int idx = atomicAdd(&s_cnt, 1);
            if (idx < CAP) cand[idx] = f;
        }
    }
    __syncthreads();

    int m = min(s_cnt, CAP);
    int P = 2;
    while (P < m) P <<= 1;
    for (int i = m + tid; i < P; i += 256) cand[i] = -1.0f;
    __syncthreads();

    for (int size = 2; size <= P; size <<= 1) {
        for (int stride = size >> 1; stride > 0; stride >>= 1) {
            for (int j = tid; j < P; j += 256) {
                int p = j ^ stride;
                if (p > j) {
                    bool down = ((j & size) == 0);
                    float a = cand[j], b = cand[p];
                    if (down ? (a < b) : (a > b)) { cand[j] = b; cand[p] = a; }
                }
            }
            __syncthreads();
        }
    }

    int nPos = s_nPos, nValid = s_nValid;
    int nc = min(min(nPos, m), kk);
    for (int pos = tid; pos < kk; pos += 256) {
        float v;
        if (pos < nc) v = cand[pos];
        else if (pos < nValid) v = 0.0f;
        else {
            int lastIdx = min(nValid, kk);
            if (lastIdx > nc) v = 0.0f;
            else v = (nc > 0) ? cand[nc - 1] : 0.0f;
        }
        out[(size_t)bat * kk + pos] = v;
    }
}

// ---------------------------------------------------------------------------
extern "C" void kernel_launch(void* const* d_in, const int* in_sizes, int n_in,
                              void* d_out, int out_size) {
    const float* inputs1 = (const float*)d_in[0];
    const float* inputs2 = (const float*)d_in[1];
    const void*  mask1   = d_in[2];
    const void*  mask2   = d_in[3];
    const float* W       = (const float*)d_in[4];
    const float* bias    = (const float*)d_in[5];
    int kk = out_size / BSZ;   // 256

    bf16 *A1h, *A1l, *H2h, *H2l, *Th, *Tl, *Wth, *Wtl;
    float* S;
    unsigned char *v1, *v2;
    cudaGetSymbolAddress((void**)&A1h, g_A1h);
    cudaGetSymbolAddress((void**)&A1l, g_A1l);
    cudaGetSymbolAddress((void**)&H2h, g_H2h);
    cudaGetSymbolAddress((void**)&H2l, g_H2l);
    cudaGetSymbolAddress((void**)&Th,  g_Th);
    cudaGetSymbolAddress((void**)&Tl,  g_Tl);
    cudaGetSymbolAddress((void**)&Wth, g_Wth);
    cudaGetSymbolAddress((void**)&Wtl, g_Wtl);
    cudaGetSymbolAddress((void**)&S,   g_S);
    cudaGetSymbolAddress((void**)&v1,  g_valid1);
    cudaGetSymbolAddress((void**)&v2,  g_valid2);

    detect_kernel<<<1, 256>>>((const unsigned long long*)mask1);
    convert_kernel<<<(MROWS + 255) / 256, 256>>>(mask1, mask2);

    int n4 = MROWS * DIM / 4;  // 4194304
    split_kernel<<<n4 / 256, 256>>>((const float4*)inputs1,
        (__nv_bfloat162*)A1h, (__nv_bfloat162*)A1l, n4);
    split_kernel<<<n4 / 256, 256>>>((const float4*)inputs2,
        (__nv_bfloat162*)H2h, (__nv_bfloat162*)H2l, n4);
    splitT_kernel<<<dim3(32, 32), dim3(32, 8)>>>(W, Wth, Wtl);

    dim3 g1(DIM / BN, MROWS / BM);        // (8, 128)
    gemm1_kernel<<<g1, NTHREADS>>>(A1h, A1l, Wth, Wtl, Th, Tl);

    dim3 g2(L2S / BN, L1S / BM, BSZ);     // (4, 4, 32)
    gemm2_kernel<<<g2, NTHREADS>>>(Th, Tl, H2h, H2l, v1, v2, bias, S);

    topk_kernel<<<BSZ, 256>>>(S, (float*)d_out, kk);
}

// round 6
// speedup vs baseline: 2.2273x; 1.3820x over previous
#include <cuda_runtime.h>
#include <cuda_bf16.h>
#include <math_constants.h>
#include <stdint.h>

typedef __nv_bfloat16 bf16;

#define L1S 512
#define L2S 512
#define BSZ 32
#define DIM 1024
#define MROWS (L1S * BSZ)   // 16384

#define BM 128
#define BN 128
#define NTHREADS 256

#define S_STAGES 4
#define ARR_BYTES 6144            // 128 rows * 24 halves * 2B
#define STAGE_BYTES (4 * ARR_BYTES)
#define AH_OFF 0
#define AL_OFF 6144
#define BH_OFF 12288
#define BL_OFF 18432
#define SMEM_DYN (S_STAGES * STAGE_BYTES)   // 98304

// ------------------------- device global scratch ---------------------------
__device__ bf16 g_A1h[(size_t)MROWS * DIM];
__device__ bf16 g_A1l[(size_t)MROWS * DIM];
__device__ bf16 g_H2h[(size_t)MROWS * DIM];
__device__ bf16 g_H2l[(size_t)MROWS * DIM];
__device__ bf16 g_Th [(size_t)MROWS * DIM];
__device__ bf16 g_Tl [(size_t)MROWS * DIM];
__device__ bf16 g_Wth[(size_t)DIM * DIM];
__device__ bf16 g_Wtl[(size_t)DIM * DIM];
__device__ float g_S[(size_t)BSZ * L1S * L2S];
__device__ unsigned char g_valid1[MROWS];
__device__ unsigned char g_valid2[L2S * BSZ];
__device__ int g_is32;

// ------------------------- mask dtype detect + convert ---------------------
__global__ void detect_kernel(const unsigned long long* __restrict__ m1) {
    __shared__ int s;
    if (threadIdx.x == 0) s = 0;
    __syncthreads();
    int bad = 0;
    for (int i = threadIdx.x; i < 8192; i += blockDim.x)
        if (m1[i] > 1ULL) bad = 1;
    if (bad) atomicOr(&s, 1);
    __syncthreads();
    if (threadIdx.x == 0) g_is32 = s;
}

__global__ void convert_kernel(const void* __restrict__ m1, const void* __restrict__ m2) {
    int i = blockIdx.x * blockDim.x + threadIdx.x;
    if (i >= MROWS) return;
    bool is32 = (g_is32 != 0);
    long long v1 = is32 ? (long long)((const int*)m1)[i] : ((const long long*)m1)[i];
    long long v2 = is32 ? (long long)((const int*)m2)[i] : ((const long long*)m2)[i];
    g_valid1[i] = (v1 == 0);
    g_valid2[i] = (v2 == 0);
}

// ------------------------- fp32 -> bf16 hi/lo split ------------------------
__device__ __forceinline__ void split1(float v, bf16& h, bf16& l) {
    h = __float2bfloat16(v);
    l = __float2bfloat16(v - __bfloat162float(h));
}

__global__ void __launch_bounds__(256) split_kernel(
    const float4* __restrict__ in, __nv_bfloat162* __restrict__ hi,
    __nv_bfloat162* __restrict__ lo, int n4) {
    int i = blockIdx.x * blockDim.x + threadIdx.x;
    if (i >= n4) return;
    float4 v = in[i];
    __nv_bfloat162 h0, h1, l0, l1;
    split1(v.x, h0.x, l0.x); split1(v.y, h0.y, l0.y);
    split1(v.z, h1.x, l1.x); split1(v.w, h1.y, l1.y);
    hi[i * 2] = h0; hi[i * 2 + 1] = h1;
    lo[i * 2] = l0; lo[i * 2 + 1] = l1;
}

__global__ void splitT_kernel(const float* __restrict__ W,
                              bf16* __restrict__ Wth, bf16* __restrict__ Wtl) {
    __shared__ float tile[32][33];
    int k0 = blockIdx.y * 32, n0 = blockIdx.x * 32;
    for (int r = threadIdx.y; r < 32; r += 8)
        tile[r][threadIdx.x] = W[(size_t)(k0 + r) * DIM + n0 + threadIdx.x];
    __syncthreads();
    for (int r = threadIdx.y; r < 32; r += 8) {
        float v = tile[threadIdx.x][r];
        bf16 h, l; split1(v, h, l);
        size_t o = (size_t)(n0 + r) * DIM + k0 + threadIdx.x;
        Wth[o] = h; Wtl[o] = l;
    }
}

// ------------------------- tensor-core GEMM core ---------------------------
__device__ __forceinline__ void cp16s(unsigned d, const void* src) {
    asm volatile("cp.async.cg.shared.global [%0], [%1], 16;\n" :: "r"(d), "l"(src));
}
__device__ __forceinline__ void ldm4(unsigned& r0, unsigned& r1, unsigned& r2,
                                     unsigned& r3, unsigned a) {
    asm volatile("ldmatrix.sync.aligned.m8n8.x4.shared.b16 {%0,%1,%2,%3}, [%4];\n"
                 : "=r"(r0), "=r"(r1), "=r"(r2), "=r"(r3) : "r"(a));
}
__device__ __forceinline__ void mma16816(float* c, const unsigned* a, const unsigned* b) {
    asm volatile(
        "mma.sync.aligned.m16n8k16.row.col.f32.bf16.bf16.f32 "
        "{%0,%1,%2,%3}, {%4,%5,%6,%7}, {%8,%9}, {%0,%1,%2,%3};\n"
        : "+f"(c[0]), "+f"(c[1]), "+f"(c[2]), "+f"(c[3])
        : "r"(a[0]), "r"(a[1]), "r"(a[2]), "r"(a[3]), "r"(b[0]), "r"(b[1]));
}

// C[BM,BN] += A[BM,K] * B[BN,K]^T with bf16x3 splits (hh + hl + lh).
// 8 warps = 2(m) x 4(n); warp tile 64x32. 4-stage cp.async pipeline + ldmatrix.
__device__ __forceinline__ void gemm_core(
    const bf16* __restrict__ pAh, const bf16* __restrict__ pAl, size_t ldA,
    const bf16* __restrict__ pBh, const bf16* __restrict__ pBl, size_t ldB,
    int K, float acc[4][4][4], char* smem) {

    const int tid = threadIdx.x;
    const int lane = tid & 31, warp = tid >> 5;
    const int WR = (warp >> 2) * 64, WC = (warp & 3) * 32;
    const unsigned sbase = (unsigned)__cvta_generic_to_shared(smem);

    // cp.async layout: each thread handles one 16B chunk per array per stage.
    const int cRow = tid >> 1, cCh = tid & 1;
    const unsigned cByte = (unsigned)(cRow * 48 + cCh * 16);
    const size_t gA = (size_t)cRow * ldA + cCh * 8;
    const size_t gB = (size_t)cRow * ldB + cCh * 8;

    // ldmatrix per-thread addresses (halves laid out with 24-half row stride)
    const int tle = lane >> 3, lr = lane & 7;
    const unsigned aByte = (unsigned)(((WR + (tle & 1) * 8 + lr) * 24 + (tle >> 1) * 8) * 2);
    const unsigned bByte = (unsigned)(((WC + (tle >> 1) * 8 + lr) * 24 + (tle & 1) * 8) * 2);

    #pragma unroll
    for (int a = 0; a < 4; a++)
        #pragma unroll
        for (int b = 0; b < 4; b++)
            #pragma unroll
            for (int c = 0; c < 4; c++) acc[a][b][c] = 0.0f;

    auto issue = [&](int kt, int stage) {
        unsigned so = sbase + stage * STAGE_BYTES + cByte;
        cp16s(so + AH_OFF, pAh + gA + kt);
        cp16s(so + AL_OFF, pAl + gA + kt);
        cp16s(so + BH_OFF, pBh + gB + kt);
        cp16s(so + BL_OFF, pBl + gB + kt);
        asm volatile("cp.async.commit_group;\n" ::);
    };

    const int NK = K >> 4;   // 64
    #pragma unroll
    for (int s = 0; s < S_STAGES - 1; s++) issue(s << 4, s);

    int stage = 0;
    for (int i = 0; i < NK; i++) {
        asm volatile("cp.async.wait_group %0;\n" :: "n"(S_STAGES - 2));
        __syncthreads();

        const unsigned st = sbase + stage * STAGE_BYTES;

        unsigned bh[4][2], bl[4][2];
        ldm4(bh[0][0], bh[0][1], bh[1][0], bh[1][1], st + BH_OFF + bByte);
        ldm4(bh[2][0], bh[2][1], bh[3][0], bh[3][1], st + BH_OFF + bByte + 768);
        ldm4(bl[0][0], bl[0][1], bl[1][0], bl[1][1], st + BL_OFF + bByte);
        ldm4(bl[2][0], bl[2][1], bl[3][0], bl[3][1], st + BL_OFF + bByte + 768);

        #pragma unroll
        for (int mt = 0; mt < 4; mt++) {
            unsigned ah[4], al[4];
            ldm4(ah[0], ah[1], ah[2], ah[3], st + AH_OFF + aByte + mt * 768);
            ldm4(al[0], al[1], al[2], al[3], st + AL_OFF + aByte + mt * 768);
            #pragma unroll
            for (int nt = 0; nt < 4; nt++) {
                mma16816(acc[mt][nt], ah, bh[nt]);
                mma16816(acc[mt][nt], ah, bl[nt]);
                mma16816(acc[mt][nt], al, bh[nt]);
            }
        }

        int nxt = i + S_STAGES - 1;
        if (nxt < NK) issue(nxt << 4, (stage + S_STAGES - 1) & (S_STAGES - 1));
        else asm volatile("cp.async.commit_group;\n" ::);
        stage = (stage + 1) & (S_STAGES - 1);
    }
}

// GEMM1: T = A1[16384,1024] * Wt[1024,1024]^T, epilogue splits to bf16 hi/lo
__global__ void __launch_bounds__(NTHREADS, 2) gemm1_kernel(
    const bf16* __restrict__ Ah, const bf16* __restrict__ Al,
    const bf16* __restrict__ Bh, const bf16* __restrict__ Bl,
    bf16* __restrict__ Th, bf16* __restrict__ Tl) {

    extern __shared__ char smem[];
    float acc[4][4][4];
    gemm_core(Ah + (size_t)blockIdx.y * BM * DIM, Al + (size_t)blockIdx.y * BM * DIM, DIM,
              Bh + (size_t)blockIdx.x * BN * DIM, Bl + (size_t)blockIdx.x * BN * DIM, DIM,
              DIM, acc, smem);

    const int lane = threadIdx.x & 31, warp = threadIdx.x >> 5;
    const int g = lane >> 2, t = lane & 3;
    const int gR = blockIdx.y * BM + (warp >> 2) * 64;
    const int gC = blockIdx.x * BN + (warp & 3) * 32;

    #pragma unroll
    for (int mt = 0; mt < 4; mt++) {
        int r0 = gR + mt * 16 + g;
        #pragma unroll
        for (int nt = 0; nt < 4; nt++) {
            int c0 = gC + nt * 8 + t * 2;
            __nv_bfloat162 h, l;
            split1(acc[mt][nt][0], h.x, l.x);
            split1(acc[mt][nt][1], h.y, l.y);
            *(__nv_bfloat162*)(Th + (size_t)r0 * DIM + c0) = h;
            *(__nv_bfloat162*)(Tl + (size_t)r0 * DIM + c0) = l;
            split1(acc[mt][nt][2], h.x, l.x);
            split1(acc[mt][nt][3], h.y, l.y);
            *(__nv_bfloat162*)(Th + (size_t)(r0 + 8) * DIM + c0) = h;
            *(__nv_bfloat162*)(Tl + (size_t)(r0 + 8) * DIM + c0) = l;
        }
    }
}

// GEMM2 (batched NT): S_b = T_b * H2_b^T + bias, relu, mask
__global__ void __launch_bounds__(NTHREADS, 2) gemm2_kernel(
    const bf16* __restrict__ Th, const bf16* __restrict__ Tl,
    const bf16* __restrict__ Hh, const bf16* __restrict__ Hl,
    const unsigned char* __restrict__ v1, const unsigned char* __restrict__ v2,
    const float* __restrict__ bias, float* __restrict__ S) {

    extern __shared__ char smem[];
    const int bat = blockIdx.z;
    const size_t ld = (size_t)BSZ * DIM;
    float acc[4][4][4];
    gemm_core(Th + (size_t)bat * DIM + (size_t)blockIdx.y * BM * ld,
              Tl + (size_t)bat * DIM + (size_t)blockIdx.y * BM * ld, ld,
              Hh + (size_t)bat * DIM + (size_t)blockIdx.x * BN * ld,
              Hl + (size_t)bat * DIM + (size_t)blockIdx.x * BN * ld, ld,
              DIM, acc, smem);

    const int lane = threadIdx.x & 31, warp = threadIdx.x >> 5;
    const int g = lane >> 2, t = lane & 3;
    const int gR = blockIdx.y * BM + (warp >> 2) * 64;
    const int gC = blockIdx.x * BN + (warp & 3) * 32;
    const float bb = bias[0];

    #pragma unroll
    for (int mt = 0; mt < 4; mt++) {
        #pragma unroll
        for (int rr = 0; rr < 2; rr++) {
            int r = gR + mt * 16 + g + rr * 8;
            bool okR = v1[r * BSZ + bat];
            #pragma unroll
            for (int nt = 0; nt < 4; nt++) {
                int c = gC + nt * 8 + t * 2;
                float va = acc[mt][nt][rr * 2 + 0];
                float vb = acc[mt][nt][rr * 2 + 1];
                va = fmaxf(va + bb, 0.0f);
                vb = fmaxf(vb + bb, 0.0f);
                if (!okR || !v2[c * BSZ + bat])       va = -CUDART_INF_F;
                if (!okR || !v2[(c + 1) * BSZ + bat]) vb = -CUDART_INF_F;
                float2 o = make_float2(va, vb);
                *(float2*)(S + ((size_t)bat * L1S + r) * L2S + c) = o;
            }
        }
    }
}

// ------------------------- top-k per batch ---------------------------------
#define NB 2048
#define CAP 4096

__global__ void __launch_bounds__(256) topk_kernel(
    const float* __restrict__ S, float* __restrict__ out, int kk) {
    int bat = blockIdx.x;
    const int NE = L1S * L2S;
    const float* Sb = S + (size_t)bat * NE;

    __shared__ int hist[NB];
    __shared__ float cand[CAP];
    __shared__ int chunkS[128];
    __shared__ int validArr[256];
    __shared__ int s_cnt, s_cutoff, s_nPos, s_nValid;

    int tid = threadIdx.x;
    for (int i = tid; i < NB; i += 256) hist[i] = 0;
    if (tid == 0) s_cnt = 0;
    __syncthreads();

    int myValid = 0;
    for (int t = tid; t < NE; t += 256) {
        float f = Sb[t];
        if (f >= 0.0f) myValid++;
        if (f > 0.0f) {
            unsigned u = __float_as_uint(f);
            atomicAdd(&hist[u >> 20], 1);
        }
    }
    validArr[tid] = myValid;
    __syncthreads();
    for (int s = 128; s > 0; s >>= 1) {
        if (tid < s) validArr[tid] += validArr[tid + s];
        __syncthreads();
    }
    if (tid < 128) {
        int s = 0;
        #pragma unroll
        for (int b = 0; b < 16; b++) s += hist[tid * 16 + b];
        chunkS[tid] = s;
    }
    __syncthreads();

    if (tid == 0) {
        int acc = 0, c = -1;
        for (int ch = 127; ch >= 0 && c < 0; ch--) {
            if (acc + chunkS[ch] >= kk) {
                for (int b = ch * 16 + 15; b >= ch * 16; b--) {
                    acc += hist[b];
                    if (acc >= kk) { c = b; break; }
                }
            } else acc += chunkS[ch];
        }
        int totalPos = 0;
        for (int ch = 0; ch < 128; ch++) totalPos += chunkS[ch];
        if (c < 0) c = 0;
        s_cutoff = c;
        s_nPos = totalPos;
        s_nValid = validArr[0];
    }
    __syncthreads();

    unsigned c = (unsigned)s_cutoff;
    for (int t = tid; t < NE; t += 256) {
        float f = Sb[t];
        if (f > 0.0f && (__float_as_uint(f) >> 20) >= c) {
            int idx = atomicAdd(&s_cnt, 1);
            if (idx < CAP) cand[idx] = f;
        }
    }
    __syncthreads();

    int m = min(s_cnt, CAP);
    int P = 2;
    while (P < m) P <<= 1;
    for (int i = m + tid; i < P; i += 256) cand[i] = -1.0f;
    __syncthreads();

    for (int size = 2; size <= P; size <<= 1) {
        for (int stride = size >> 1; stride > 0; stride >>= 1) {
            for (int j = tid; j < P; j += 256) {
                int p = j ^ stride;
                if (p > j) {
                    bool down = ((j & size) == 0);
                    float a = cand[j], b = cand[p];
                    if (down ? (a < b) : (a > b)) { cand[j] = b; cand[p] = a; }
                }
            }
            __syncthreads();
        }
    }

    int nPos = s_nPos, nValid = s_nValid;
    int nc = min(min(nPos, m), kk);
    for (int pos = tid; pos < kk; pos += 256) {
        float v;
        if (pos < nc) v = cand[pos];
        else if (pos < nValid) v = 0.0f;
        else {
            int lastIdx = min(nValid, kk);
            if (lastIdx > nc) v = 0.0f;
            else v = (nc > 0) ? cand[nc - 1] : 0.0f;
        }
        out[(size_t)bat * kk + pos] = v;
    }
}

// ---------------------------------------------------------------------------
extern "C" void kernel_launch(void* const* d_in, const int* in_sizes, int n_in,
                              void* d_out, int out_size) {
    const float* inputs1 = (const float*)d_in[0];
    const float* inputs2 = (const float*)d_in[1];
    const void*  mask1   = d_in[2];
    const void*  mask2   = d_in[3];
    const float* W       = (const float*)d_in[4];
    const float* bias    = (const float*)d_in[5];
    int kk = out_size / BSZ;   // 256

    bf16 *A1h, *A1l, *H2h, *H2l, *Th, *Tl, *Wth, *Wtl;
    float* S;
    unsigned char *v1, *v2;
    cudaGetSymbolAddress((void**)&A1h, g_A1h);
    cudaGetSymbolAddress((void**)&A1l, g_A1l);
    cudaGetSymbolAddress((void**)&H2h, g_H2h);
    cudaGetSymbolAddress((void**)&H2l, g_H2l);
    cudaGetSymbolAddress((void**)&Th,  g_Th);
    cudaGetSymbolAddress((void**)&Tl,  g_Tl);
    cudaGetSymbolAddress((void**)&Wth, g_Wth);
    cudaGetSymbolAddress((void**)&Wtl, g_Wtl);
    cudaGetSymbolAddress((void**)&S,   g_S);
    cudaGetSymbolAddress((void**)&v1,  g_valid1);
    cudaGetSymbolAddress((void**)&v2,  g_valid2);

    cudaFuncSetAttribute(gemm1_kernel, cudaFuncAttributeMaxDynamicSharedMemorySize, SMEM_DYN);
    cudaFuncSetAttribute(gemm2_kernel, cudaFuncAttributeMaxDynamicSharedMemorySize, SMEM_DYN);

    detect_kernel<<<1, 256>>>((const unsigned long long*)mask1);
    convert_kernel<<<(MROWS + 255) / 256, 256>>>(mask1, mask2);

    int n4 = MROWS * DIM / 4;  // 4194304
    split_kernel<<<n4 / 256, 256>>>((const float4*)inputs1,
        (__nv_bfloat162*)A1h, (__nv_bfloat162*)A1l, n4);
    split_kernel<<<n4 / 256, 256>>>((const float4*)inputs2,
        (__nv_bfloat162*)H2h, (__nv_bfloat162*)H2l, n4);
    splitT_kernel<<<dim3(32, 32), dim3(32, 8)>>>(W, Wth, Wtl);

    dim3 g1(DIM / BN, MROWS / BM);        // (8, 128)
    gemm1_kernel<<<g1, NTHREADS, SMEM_DYN>>>(A1h, A1l, Wth, Wtl, Th, Tl);

    dim3 g2(L2S / BN, L1S / BM, BSZ);     // (4, 4, 32)
    gemm2_kernel<<<g2, NTHREADS, SMEM_DYN>>>(Th, Tl, H2h, H2l, v1, v2, bias, S);

    topk_kernel<<<BSZ, 256>>>(S, (float*)d_out, kk);
}

// round 8
// speedup vs baseline: 2.5606x; 1.1497x over previous
#include <cuda_runtime.h>
#include <cuda_bf16.h>
#include <math_constants.h>
#include <stdint.h>

typedef __nv_bfloat16 bf16;

#define L1S 512
#define L2S 512
#define BSZ 32
#define DIM 1024
#define MROWS (L1S * BSZ)   // 16384

#define BM 128
#define BN 128
#define NTHREADS 256

#define S_STAGES 4
#define ARR_BYTES 6144            // 128 rows * 24 halves * 2B
#define STAGE_BYTES (4 * ARR_BYTES)
#define AH_OFF 0
#define AL_OFF 6144
#define BH_OFF 12288
#define BL_OFF 18432
#define SMEM_DYN (S_STAGES * STAGE_BYTES)   // 98304

// ------------------------- device global scratch ---------------------------
__device__ bf16 g_A1h[(size_t)MROWS * DIM];
__device__ bf16 g_A1l[(size_t)MROWS * DIM];
__device__ bf16 g_H2h[(size_t)MROWS * DIM];
__device__ bf16 g_H2l[(size_t)MROWS * DIM];
__device__ bf16 g_Th [(size_t)MROWS * DIM];
__device__ bf16 g_Tl [(size_t)MROWS * DIM];
__device__ bf16 g_Wth[(size_t)DIM * DIM];
__device__ bf16 g_Wtl[(size_t)DIM * DIM];
__device__ float g_S[(size_t)BSZ * L1S * L2S];
__device__ int g_is32;
// compaction state
__device__ int g_n1[BSZ];
__device__ int g_n2[BSZ];
__device__ int g_nG;
__device__ int g_idx1[BSZ * L1S];
__device__ int g_idx2[BSZ * L2S];
__device__ int g_gidx[MROWS];

// ------------------------- mask dtype detect (+ counter zero) --------------
__global__ void detect_kernel(const unsigned long long* __restrict__ m1) {
    __shared__ int s;
    if (threadIdx.x == 0) s = 0;
    __syncthreads();
    int bad = 0;
    for (int i = threadIdx.x; i < 8192; i += blockDim.x)
        if (m1[i] > 1ULL) bad = 1;
    if (bad) atomicOr(&s, 1);
    __syncthreads();
    if (threadIdx.x == 0) { g_is32 = s; g_nG = 0; }
    if (threadIdx.x < BSZ) { g_n1[threadIdx.x] = 0; g_n2[threadIdx.x] = 0; }
}

// One block per batch; 512 threads = positions. Unordered append (top-k is
// permutation invariant, so output stays deterministic).
__global__ void __launch_bounds__(512) compact_kernel(
    const void* __restrict__ m1, const void* __restrict__ m2) {
    int b = blockIdx.x, l = threadIdx.x;
    bool is32 = (g_is32 != 0);
    int i = l * BSZ + b;
    long long v1 = is32 ? (long long)((const int*)m1)[i] : ((const long long*)m1)[i];
    long long v2 = is32 ? (long long)((const int*)m2)[i] : ((const long long*)m2)[i];
    if (v1 == 0) {
        int p = atomicAdd(&g_n1[b], 1);
        g_idx1[b * L1S + p] = l;
        int q = atomicAdd(&g_nG, 1);
        g_gidx[q] = i;
    }
    if (v2 == 0) {
        int p = atomicAdd(&g_n2[b], 1);
        g_idx2[b * L2S + p] = l;
    }
}

// ------------------------- fp32 -> bf16 hi/lo split ------------------------
__device__ __forceinline__ void split1(float v, bf16& h, bf16& l) {
    h = __float2bfloat16(v);
    l = __float2bfloat16(v - __bfloat162float(h));
}

__global__ void __launch_bounds__(256) split_kernel(
    const float4* __restrict__ in, __nv_bfloat162* __restrict__ hi,
    __nv_bfloat162* __restrict__ lo, int n4) {
    int i = blockIdx.x * blockDim.x + threadIdx.x;
    if (i >= n4) return;
    float4 v = in[i];
    __nv_bfloat162 h0, h1, l0, l1;
    split1(v.x, h0.x, l0.x); split1(v.y, h0.y, l0.y);
    split1(v.z, h1.x, l1.x); split1(v.w, h1.y, l1.y);
    hi[i * 2] = h0; hi[i * 2 + 1] = h1;
    lo[i * 2] = l0; lo[i * 2 + 1] = l1;
}

__global__ void splitT_kernel(const float* __restrict__ W,
                              bf16* __restrict__ Wth, bf16* __restrict__ Wtl) {
    __shared__ float tile[32][33];
    int k0 = blockIdx.y * 32, n0 = blockIdx.x * 32;
    for (int r = threadIdx.y; r < 32; r += 8)
        tile[r][threadIdx.x] = W[(size_t)(k0 + r) * DIM + n0 + threadIdx.x];
    __syncthreads();
    for (int r = threadIdx.y; r < 32; r += 8) {
        float v = tile[threadIdx.x][r];
        bf16 h, l; split1(v, h, l);
        size_t o = (size_t)(n0 + r) * DIM + k0 + threadIdx.x;
        Wth[o] = h; Wtl[o] = l;
    }
}

// ------------------------- tensor-core GEMM core ---------------------------
__device__ __forceinline__ void cp16s(unsigned d, const void* src) {
    asm volatile("cp.async.cg.shared.global [%0], [%1], 16;\n" :: "r"(d), "l"(src));
}
__device__ __forceinline__ void ldm4(unsigned& r0, unsigned& r1, unsigned& r2,
                                     unsigned& r3, unsigned a) {
    asm volatile("ldmatrix.sync.aligned.m8n8.x4.shared.b16 {%0,%1,%2,%3}, [%4];\n"
                 : "=r"(r0), "=r"(r1), "=r"(r2), "=r"(r3) : "r"(a));
}
__device__ __forceinline__ void mma16816(float* c, const unsigned* a, const unsigned* b) {
    asm volatile(
        "mma.sync.aligned.m16n8k16.row.col.f32.bf16.bf16.f32 "
        "{%0,%1,%2,%3}, {%4,%5,%6,%7}, {%8,%9}, {%0,%1,%2,%3};\n"
        : "+f"(c[0]), "+f"(c[1]), "+f"(c[2]), "+f"(c[3])
        : "r"(a[0]), "r"(a[1]), "r"(a[2]), "r"(a[3]), "r"(b[0]), "r"(b[1]));
}

// C[BM,BN] += A[BM,K] * B[BN,K]^T with bf16x3 splits (hh + hl + lh).
// Per-thread row base pointers tAh/tAl/tBh/tBl (gathered rows), chunk offset
// included. 8 warps = 2(m) x 4(n); warp tile 64x32. 4-stage cp.async pipeline.
__device__ __forceinline__ void gemm_core(
    const bf16* __restrict__ tAh, const bf16* __restrict__ tAl,
    const bf16* __restrict__ tBh, const bf16* __restrict__ tBl,
    int K, float acc[4][4][4], char* smem) {

    const int tid = threadIdx.x;
    const int lane = tid & 31, warp = tid >> 5;
    const int WR = (warp >> 2) * 64, WC = (warp & 3) * 32;
    const unsigned sbase = (unsigned)__cvta_generic_to_shared(smem);

    const int cRow = tid >> 1, cCh = tid & 1;
    const unsigned cByte = (unsigned)(cRow * 48 + cCh * 16);

    const int tle = lane >> 3, lr = lane & 7;
    const unsigned aByte = (unsigned)(((WR + (tle & 1) * 8 + lr) * 24 + (tle >> 1) * 8) * 2);
    const unsigned bByte = (unsigned)(((WC + (tle >> 1) * 8 + lr) * 24 + (tle & 1) * 8) * 2);

    #pragma unroll
    for (int a = 0; a < 4; a++)
        #pragma unroll
        for (int b = 0; b < 4; b++)
            #pragma unroll
            for (int c = 0; c < 4; c++) acc[a][b][c] = 0.0f;

    auto issue = [&](int kt, int stage) {
        unsigned so = sbase + stage * STAGE_BYTES + cByte;
        cp16s(so + AH_OFF, tAh + kt);
        cp16s(so + AL_OFF, tAl + kt);
        cp16s(so + BH_OFF, tBh + kt);
        cp16s(so + BL_OFF, tBl + kt);
        asm volatile("cp.async.commit_group;\n" ::);
    };

    const int NK = K >> 4;   // 64
    #pragma unroll
    for (int s = 0; s < S_STAGES - 1; s++) issue(s << 4, s);

    int stage = 0;
    for (int i = 0; i < NK; i++) {
        asm volatile("cp.async.wait_group %0;\n" :: "n"(S_STAGES - 2));
        __syncthreads();

        const unsigned st = sbase + stage * STAGE_BYTES;

        unsigned bh[4][2], bl[4][2];
        ldm4(bh[0][0], bh[0][1], bh[1][0], bh[1][1], st + BH_OFF + bByte);
        ldm4(bh[2][0], bh[2][1], bh[3][0], bh[3][1], st + BH_OFF + bByte + 768);
        ldm4(bl[0][0], bl[0][1], bl[1][0], bl[1][1], st + BL_OFF + bByte);
        ldm4(bl[2][0], bl[2][1], bl[3][0], bl[3][1], st + BL_OFF + bByte + 768);

        #pragma unroll
        for (int mt = 0; mt < 4; mt++) {
            unsigned ah[4], al[4];
            ldm4(ah[0], ah[1], ah[2], ah[3], st + AH_OFF + aByte + mt * 768);
            ldm4(al[0], al[1], al[2], al[3], st + AL_OFF + aByte + mt * 768);
            #pragma unroll
            for (int nt = 0; nt < 4; nt++) {
                mma16816(acc[mt][nt], ah, bh[nt]);
                mma16816(acc[mt][nt], ah, bl[nt]);
                mma16816(acc[mt][nt], al, bh[nt]);
            }
        }

        int nxt = i + S_STAGES - 1;
        if (nxt < NK) issue(nxt << 4, (stage + S_STAGES - 1) & (S_STAGES - 1));
        else asm volatile("cp.async.commit_group;\n" ::);
        stage = (stage + 1) & (S_STAGES - 1);
    }
}

// GEMM1 over compacted valid rows: T[gidx[p]] = A1[gidx[p]] * Wt^T (split out)
__global__ void __launch_bounds__(NTHREADS, 2) gemm1_kernel(
    const bf16* __restrict__ Ah, const bf16* __restrict__ Al,
    const bf16* __restrict__ Bh, const bf16* __restrict__ Bl,
    bf16* __restrict__ Th, bf16* __restrict__ Tl) {

    const int ng = g_nG;
    if ((int)blockIdx.y * BM >= ng) return;

    extern __shared__ char smem[];
    const int tid = threadIdx.x;
    const int cRow = tid >> 1, cCh = tid & 1;

    const int ar = min((int)blockIdx.y * BM + cRow, ng - 1);
    const int aIdx = g_gidx[ar];
    const bf16* tAh = Ah + (size_t)aIdx * DIM + cCh * 8;
    const bf16* tAl = Al + (size_t)aIdx * DIM + cCh * 8;
    const bf16* tBh = Bh + (size_t)(blockIdx.x * BN + cRow) * DIM + cCh * 8;
    const bf16* tBl = Bl + (size_t)(blockIdx.x * BN + cRow) * DIM + cCh * 8;

    float acc[4][4][4];
    gemm_core(tAh, tAl, tBh, tBl, DIM, acc, smem);

    const int lane = tid & 31, warp = tid >> 5;
    const int g = lane >> 2, t = lane & 3;
    const int pR = blockIdx.y * BM + (warp >> 2) * 64;
    const int gC = blockIdx.x * BN + (warp & 3) * 32;

    #pragma unroll
    for (int mt = 0; mt < 4; mt++) {
        #pragma unroll
        for (int rr = 0; rr < 2; rr++) {
            int p = pR + mt * 16 + g + rr * 8;
            if (p >= ng) continue;
            int row = g_gidx[p];
            #pragma unroll
            for (int nt = 0; nt < 4; nt++) {
                int c0 = gC + nt * 8 + t * 2;
                __nv_bfloat162 h, l;
                split1(acc[mt][nt][rr * 2 + 0], h.x, l.x);
                split1(acc[mt][nt][rr * 2 + 1], h.y, l.y);
                *(__nv_bfloat162*)(Th + (size_t)row * DIM + c0) = h;
                *(__nv_bfloat162*)(Tl + (size_t)row * DIM + c0) = l;
            }
        }
    }
}

// GEMM2 (batched NT, compacted): S[b][i][j] = relu(T[idx1[i]] . H2[idx2[j]] + b)
__global__ void __launch_bounds__(NTHREADS, 2) gemm2_kernel(
    const bf16* __restrict__ Th, const bf16* __restrict__ Tl,
    const bf16* __restrict__ Hh, const bf16* __restrict__ Hl,
    const float* __restrict__ bias, float* __restrict__ S) {

    const int bat = blockIdx.z;
    const int n1 = g_n1[bat], n2 = g_n2[bat];
    if ((int)blockIdx.y * BM >= n1 || (int)blockIdx.x * BN >= n2) return;

    extern __shared__ char smem[];
    const int tid = threadIdx.x;
    const int cRow = tid >> 1, cCh = tid & 1;

    const int ai = g_idx1[bat * L1S + min((int)blockIdx.y * BM + cRow, n1 - 1)];
    const int bi = g_idx2[bat * L2S + min((int)blockIdx.x * BN + cRow, n2 - 1)];
    const bf16* tAh = Th + ((size_t)ai * BSZ + bat) * DIM + cCh * 8;
    const bf16* tAl = Tl + ((size_t)ai * BSZ + bat) * DIM + cCh * 8;
    const bf16* tBh = Hh + ((size_t)bi * BSZ + bat) * DIM + cCh * 8;
    const bf16* tBl = Hl + ((size_t)bi * BSZ + bat) * DIM + cCh * 8;

    float acc[4][4][4];
    gemm_core(tAh, tAl, tBh, tBl, DIM, acc, smem);

    const int lane = tid & 31, warp = tid >> 5;
    const int g = lane >> 2, t = lane & 3;
    const int gR = blockIdx.y * BM + (warp >> 2) * 64;
    const int gC = blockIdx.x * BN + (warp & 3) * 32;
    const float bb = bias[0];

    #pragma unroll
    for (int mt = 0; mt < 4; mt++) {
        #pragma unroll
        for (int rr = 0; rr < 2; rr++) {
            int r = gR + mt * 16 + g + rr * 8;
            #pragma unroll
            for (int nt = 0; nt < 4; nt++) {
                int c = gC + nt * 8 + t * 2;
                float va = fmaxf(acc[mt][nt][rr * 2 + 0] + bb, 0.0f);
                float vb = fmaxf(acc[mt][nt][rr * 2 + 1] + bb, 0.0f);
                *(float2*)(S + ((size_t)bat * L1S + r) * L2S + c) = make_float2(va, vb);
            }
        }
    }
}

// ------------------------- top-k per batch (compacted region) --------------
#define NB 2048
#define CAP 4096

__global__ void __launch_bounds__(256) topk_kernel(
    const float* __restrict__ S, float* __restrict__ out, int kk) {
    int bat = blockIdx.x;
    const float* Sb = S + (size_t)bat * L1S * L2S;
    const int n1 = g_n1[bat], n2 = g_n2[bat];
    const int span = n1 * L2S;
    const long long nValid = (long long)n1 * n2;

    __shared__ int hist[NB];
    __shared__ float cand[CAP];
    __shared__ int chunkS[128];
    __shared__ int s_cnt, s_cutoff, s_nPos;

    int tid = threadIdx.x;
    for (int i = tid; i < NB; i += 256) hist[i] = 0;
    if (tid == 0) s_cnt = 0;
    __syncthreads();

    for (int t = tid; t < span; t += 256) {
        if ((t & (L2S - 1)) >= n2) continue;
        float f = Sb[t];
        if (f > 0.0f) {
            unsigned u = __float_as_uint(f);
            atomicAdd(&hist[u >> 20], 1);
        }
    }
    __syncthreads();
    if (tid < 128) {
        int s = 0;
        #pragma unroll
        for (int b = 0; b < 16; b++) s += hist[tid * 16 + b];
        chunkS[tid] = s;
    }
    __syncthreads();

    if (tid == 0) {
        int acc = 0, c = -1;
        for (int ch = 127; ch >= 0 && c < 0; ch--) {
            if (acc + chunkS[ch] >= kk) {
                for (int b = ch * 16 + 15; b >= ch * 16; b--) {
                    acc += hist[b];
                    if (acc >= kk) { c = b; break; }
                }
            } else acc += chunkS[ch];
        }
        int totalPos = 0;
        for (int ch = 0; ch < 128; ch++) totalPos += chunkS[ch];
        if (c < 0) c = 0;
        s_cutoff = c;
        s_nPos = totalPos;
    }
    __syncthreads();

    unsigned c = (unsigned)s_cutoff;
    for (int t = tid; t < span; t += 256) {
        if ((t & (L2S - 1)) >= n2) continue;
        float f = Sb[t];
        if (f > 0.0f && (__float_as_uint(f) >> 20) >= c) {
            int idx = atomicAdd(&s_cnt, 1);
            if (idx < CAP) cand[idx] = f;
        }
    }
    __syncthreads();

    int m = min(s_cnt, CAP);
    int P = 2;
    while (P < m) P <<= 1;
    for (int i = m + tid; i < P; i += 256) cand[i] = -1.0f;
    __syncthreads();

    for (int size = 2; size <= P; size <<= 1) {
        for (int stride = size >> 1; stride > 0; stride >>= 1) {
            for (int j = tid; j < P; j += 256) {
                int p = j ^ stride;
                if (p > j) {
                    bool down = ((j & size) == 0);
                    float a = cand[j], b = cand[p];
                    if (down ? (a < b) : (a > b)) { cand[j] = b; cand[p] = a; }
                }
            }
            __syncthreads();
        }
    }

    int nPos = s_nPos;
    int nc = min(min(nPos, m), kk);
    for (int pos = tid; pos < kk; pos += 256) {
        float v;
        if (pos < nc) v = cand[pos];
        else if ((long long)pos < nValid) v = 0.0f;   // remaining valid are relu-zeros
        else v = (nc > 0) ? cand[nc - 1] : 0.0f;      // -inf tail fill
        out[(size_t)bat * kk + pos] = v;
    }
}

// ---------------------------------------------------------------------------
extern "C" void kernel_launch(void* const* d_in, const int* in_sizes, int n_in,
                              void* d_out, int out_size) {
    const float* inputs1 = (const float*)d_in[0];
    const float* inputs2 = (const float*)d_in[1];
    const void*  mask1   = d_in[2];
    const void*  mask2   = d_in[3];
    const float* W       = (const float*)d_in[4];
    const float* bias    = (const float*)d_in[5];
    int kk = out_size / BSZ;   // 256

    bf16 *A1h, *A1l, *H2h, *H2l, *Th, *Tl, *Wth, *Wtl;
    float* S;
    cudaGetSymbolAddress((void**)&A1h, g_A1h);
    cudaGetSymbolAddress((void**)&A1l, g_A1l);
    cudaGetSymbolAddress((void**)&H2h, g_H2h);
    cudaGetSymbolAddress((void**)&H2l, g_H2l);
    cudaGetSymbolAddress((void**)&Th,  g_Th);
    cudaGetSymbolAddress((void**)&Tl,  g_Tl);
    cudaGetSymbolAddress((void**)&Wth, g_Wth);
    cudaGetSymbolAddress((void**)&Wtl, g_Wtl);
    cudaGetSymbolAddress((void**)&S,   g_S);

    cudaFuncSetAttribute(gemm1_kernel, cudaFuncAttributeMaxDynamicSharedMemorySize, SMEM_DYN);
    cudaFuncSetAttribute(gemm2_kernel, cudaFuncAttributeMaxDynamicSharedMemorySize, SMEM_DYN);

    detect_kernel<<<1, 256>>>((const unsigned long long*)mask1);
    compact_kernel<<<BSZ, 512>>>(mask1, mask2);

    int n4 = MROWS * DIM / 4;  // 4194304
    split_kernel<<<n4 / 256, 256>>>((const float4*)inputs1,
        (__nv_bfloat162*)A1h, (__nv_bfloat162*)A1l, n4);
    split_kernel<<<n4 / 256, 256>>>((const float4*)inputs2,
        (__nv_bfloat162*)H2h, (__nv_bfloat162*)H2l, n4);
    splitT_kernel<<<dim3(32, 32), dim3(32, 8)>>>(W, Wth, Wtl);

    dim3 g1(DIM / BN, MROWS / BM);        // (8, 128), CTAs beyond g_nG exit
    gemm1_kernel<<<g1, NTHREADS, SMEM_DYN>>>(A1h, A1l, Wth, Wtl, Th, Tl);

    dim3 g2(L2S / BN, L1S / BM, BSZ);     // (4, 4, 32), CTAs beyond counts exit
    gemm2_kernel<<<g2, NTHREADS, SMEM_DYN>>>(Th, Tl, H2h, H2l, bias, S);

    topk_kernel<<<BSZ, 256>>>(S, (float*)d_out, kk);
}

// round 9
// speedup vs baseline: 2.9095x; 1.1363x over previous
#include <cuda_runtime.h>
#include <cuda_fp16.h>
#include <math_constants.h>
#include <stdint.h>

#define L1S 512
#define L2S 512
#define BSZ 32
#define DIM 1024
#define MROWS (L1S * BSZ)   // 16384

#define BM 128
#define BN 128
#define NTHREADS 256

#define S_STAGES 5
#define ARR_BYTES 6144            // 128 rows * 24 halves * 2B
#define STAGE_BYTES (3 * ARR_BYTES)   // AH, AL, BH
#define AH_OFF 0
#define AL_OFF 6144
#define BH_OFF 12288
#define SMEM_DYN (S_STAGES * STAGE_BYTES)   // 92160

// ------------------------- device global scratch ---------------------------
__device__ __half g_A1h[(size_t)MROWS * DIM];   // global-packed valid rows
__device__ __half g_A1l[(size_t)MROWS * DIM];
__device__ __half g_H2h[(size_t)MROWS * DIM];   // batch-packed valid rows
__device__ __half g_Th [(size_t)MROWS * DIM];   // batch-packed T
__device__ __half g_Tl [(size_t)MROWS * DIM];
__device__ __half g_Wh [(size_t)DIM * DIM];     // W^T, fp16 hi only
__device__ float g_S[(size_t)BSZ * L1S * L2S];
__device__ int g_is32;
__device__ int g_n1[BSZ];
__device__ int g_n2[BSZ];
__device__ int g_nG;
__device__ int g_idx2[BSZ * L2S];
__device__ int g_gidx[MROWS];   // packed p -> orig flat row (l*BSZ+b)
__device__ int g_gmap[MROWS];   // packed p -> batch-packed T row (b*L1S+pos)

// ------------------------- mask dtype detect (+ counter zero) --------------
__global__ void detect_kernel(const unsigned long long* __restrict__ m1) {
    __shared__ int s;
    if (threadIdx.x == 0) s = 0;
    __syncthreads();
    int bad = 0;
    for (int i = threadIdx.x; i < 8192; i += blockDim.x)
        if (m1[i] > 1ULL) bad = 1;
    if (bad) atomicOr(&s, 1);
    __syncthreads();
    if (threadIdx.x == 0) { g_is32 = s; g_nG = 0; }
    if (threadIdx.x < BSZ) { g_n1[threadIdx.x] = 0; g_n2[threadIdx.x] = 0; }
}

// One block per batch; thread = position. Unordered append (top-k is
// permutation invariant; per-row results are order-independent).
__global__ void __launch_bounds__(512) compact_kernel(
    const void* __restrict__ m1, const void* __restrict__ m2) {
    int b = blockIdx.x, l = threadIdx.x;
    bool is32 = (g_is32 != 0);
    int i = l * BSZ + b;
    long long v1 = is32 ? (long long)((const int*)m1)[i] : ((const long long*)m1)[i];
    long long v2 = is32 ? (long long)((const int*)m2)[i] : ((const long long*)m2)[i];
    if (v1 == 0) {
        int p = atomicAdd(&g_n1[b], 1);
        int q = atomicAdd(&g_nG, 1);
        g_gidx[q] = i;
        g_gmap[q] = b * L1S + p;
    }
    if (v2 == 0) {
        int p = atomicAdd(&g_n2[b], 1);
        g_idx2[b * L2S + p] = l;
    }
}

// ------------------------- fp32 -> fp16 hi/lo split ------------------------
__device__ __forceinline__ void split1h(float v, __half& h, __half& l) {
    h = __float2half_rn(v);
    l = __float2half_rn(v - __half2float(h));
}

// Gather-split inputs1: packed row p <- orig row g_gidx[p]; hi + lo.
__global__ void __launch_bounds__(256) splitA1_kernel(const float4* __restrict__ in) {
    int p = blockIdx.x;
    if (p >= g_nG) return;
    int orig = g_gidx[p];
    int t = threadIdx.x;
    float4 v = in[(size_t)orig * (DIM / 4) + t];
    __half2 h0, h1, l0, l1;
    split1h(v.x, h0.x, l0.x); split1h(v.y, h0.y, l0.y);
    split1h(v.z, h1.x, l1.x); split1h(v.w, h1.y, l1.y);
    __half2* hp = (__half2*)g_A1h + (size_t)p * (DIM / 2) + t * 2;
    __half2* lp = (__half2*)g_A1l + (size_t)p * (DIM / 2) + t * 2;
    hp[0] = h0; hp[1] = h1;
    lp[0] = l0; lp[1] = l1;
}

// Gather inputs2 (hi only): batch-packed row (b,pos) <- orig row idx2.
__global__ void __launch_bounds__(256) splitH2_kernel(const float4* __restrict__ in) {
    int p2 = blockIdx.x;
    int bat = p2 >> 9, pos = p2 & (L2S - 1);
    if (pos >= g_n2[bat]) return;
    int l = g_idx2[bat * L2S + pos];
    int t = threadIdx.x;
    float4 v = in[((size_t)l * BSZ + bat) * (DIM / 4) + t];
    __half2 h0, h1;
    h0.x = __float2half_rn(v.x); h0.y = __float2half_rn(v.y);
    h1.x = __float2half_rn(v.z); h1.y = __float2half_rn(v.w);
    __half2* hp = (__half2*)g_H2h + (size_t)p2 * (DIM / 2) + t * 2;
    hp[0] = h0; hp[1] = h1;
}

// transpose W[k][n] -> Wt[n][k], fp16 hi only
__global__ void splitT_kernel(const float* __restrict__ W) {
    __shared__ float tile[32][33];
    int k0 = blockIdx.y * 32, n0 = blockIdx.x * 32;
    for (int r = threadIdx.y; r < 32; r += 8)
        tile[r][threadIdx.x] = W[(size_t)(k0 + r) * DIM + n0 + threadIdx.x];
    __syncthreads();
    for (int r = threadIdx.y; r < 32; r += 8)
        g_Wh[(size_t)(n0 + r) * DIM + k0 + threadIdx.x] =
            __float2half_rn(tile[threadIdx.x][r]);
}

// ------------------------- tensor-core GEMM core ---------------------------
__device__ __forceinline__ void cp16s(unsigned d, const void* src) {
    asm volatile("cp.async.cg.shared.global [%0], [%1], 16;\n" :: "r"(d), "l"(src));
}
__device__ __forceinline__ void ldm4(unsigned& r0, unsigned& r1, unsigned& r2,
                                     unsigned& r3, unsigned a) {
    asm volatile("ldmatrix.sync.aligned.m8n8.x4.shared.b16 {%0,%1,%2,%3}, [%4];\n"
                 : "=r"(r0), "=r"(r1), "=r"(r2), "=r"(r3) : "r"(a));
}
__device__ __forceinline__ void mma16816(float* c, const unsigned* a, const unsigned* b) {
    asm volatile(
        "mma.sync.aligned.m16n8k16.row.col.f32.f16.f16.f32 "
        "{%0,%1,%2,%3}, {%4,%5,%6,%7}, {%8,%9}, {%0,%1,%2,%3};\n"
        : "+f"(c[0]), "+f"(c[1]), "+f"(c[2]), "+f"(c[3])
        : "r"(a[0]), "r"(a[1]), "r"(a[2]), "r"(a[3]), "r"(b[0]), "r"(b[1]));
}

// C[BM,BN] += (Ah+Al)[BM,K] * Bh[BN,K]^T, fp16 2-term, fp32 accum.
// 8 warps = 2(m) x 4(n); warp tile 64x32. 5-stage cp.async pipeline + ldmatrix.
__device__ __forceinline__ void gemm_core(
    const __half* __restrict__ tAh, const __half* __restrict__ tAl,
    const __half* __restrict__ tBh,
    float acc[4][4][4], char* smem) {

    const int tid = threadIdx.x;
    const int lane = tid & 31, warp = tid >> 5;
    const int WR = (warp >> 2) * 64, WC = (warp & 3) * 32;
    const unsigned sbase = (unsigned)__cvta_generic_to_shared(smem);

    const unsigned cByte = (unsigned)((tid >> 1) * 48 + (tid & 1) * 16);

    const int tle = lane >> 3, lr = lane & 7;
    const unsigned aByte = (unsigned)(((WR + (tle & 1) * 8 + lr) * 24 + (tle >> 1) * 8) * 2);
    const unsigned bByte = (unsigned)(((WC + (tle >> 1) * 8 + lr) * 24 + (tle & 1) * 8) * 2);

    #pragma unroll
    for (int a = 0; a < 4; a++)
        #pragma unroll
        for (int b = 0; b < 4; b++)
            #pragma unroll
            for (int c = 0; c < 4; c++) acc[a][b][c] = 0.0f;

    auto issue = [&](int kt, int stage) {
        unsigned so = sbase + stage * STAGE_BYTES + cByte;
        cp16s(so + AH_OFF, tAh + kt);
        cp16s(so + AL_OFF, tAl + kt);
        cp16s(so + BH_OFF, tBh + kt);
        asm volatile("cp.async.commit_group;\n" ::);
    };

    const int NK = DIM >> 4;   // 64
    #pragma unroll
    for (int s = 0; s < S_STAGES - 1; s++) issue(s << 4, s);

    int stage = 0, wstage = S_STAGES - 1;
    for (int i = 0; i < NK; i++) {
        asm volatile("cp.async.wait_group %0;\n" :: "n"(S_STAGES - 2));
        __syncthreads();

        const unsigned st = sbase + stage * STAGE_BYTES;

        unsigned bh[4][2];
        ldm4(bh[0][0], bh[0][1], bh[1][0], bh[1][1], st + BH_OFF + bByte);
        ldm4(bh[2][0], bh[2][1], bh[3][0], bh[3][1], st + BH_OFF + bByte + 768);

        #pragma unroll
        for (int mt = 0; mt < 4; mt++) {
            unsigned ah[4], al[4];
            ldm4(ah[0], ah[1], ah[2], ah[3], st + AH_OFF + aByte + mt * 768);
            ldm4(al[0], al[1], al[2], al[3], st + AL_OFF + aByte + mt * 768);
            #pragma unroll
            for (int nt = 0; nt < 4; nt++) {
                mma16816(acc[mt][nt], ah, bh[nt]);
                mma16816(acc[mt][nt], al, bh[nt]);
            }
        }

        int nxt = i + S_STAGES - 1;
        if (nxt < NK) {
            issue(nxt << 4, wstage);
        } else {
            asm volatile("cp.async.commit_group;\n" ::);
        }
        if (++stage == S_STAGES) stage = 0;
        if (++wstage == S_STAGES) wstage = 0;
    }
}

// GEMM1: T[gmap[p]] = A1packed[p] * Wt^T; output split to fp16 hi/lo.
__global__ void __launch_bounds__(NTHREADS, 2) gemm1_kernel() {
    const int ng = g_nG;
    if ((int)blockIdx.y * BM >= ng) return;

    extern __shared__ char smem[];
    const int tid = threadIdx.x;
    const int cRow = tid >> 1, cCh = tid & 1;

    const int ar = min((int)blockIdx.y * BM + cRow, ng - 1);
    const __half* tAh = g_A1h + (size_t)ar * DIM + cCh * 8;
    const __half* tAl = g_A1l + (size_t)ar * DIM + cCh * 8;
    const __half* tBh = g_Wh + (size_t)(blockIdx.x * BN + cRow) * DIM + cCh * 8;

    float acc[4][4][4];
    gemm_core(tAh, tAl, tBh, acc, smem);

    const int lane = tid & 31, warp = tid >> 5;
    const int g = lane >> 2, t = lane & 3;
    const int pR = blockIdx.y * BM + (warp >> 2) * 64;
    const int gC = blockIdx.x * BN + (warp & 3) * 32;

    #pragma unroll
    for (int mt = 0; mt < 4; mt++) {
        #pragma unroll
        for (int rr = 0; rr < 2; rr++) {
            int p = pR + mt * 16 + g + rr * 8;
            if (p >= ng) continue;
            size_t base = (size_t)g_gmap[p] * DIM;
            #pragma unroll
            for (int nt = 0; nt < 4; nt++) {
                int c0 = gC + nt * 8 + t * 2;
                __half2 h, l;
                split1h(acc[mt][nt][rr * 2 + 0], h.x, l.x);
                split1h(acc[mt][nt][rr * 2 + 1], h.y, l.y);
                *(__half2*)(g_Th + base + c0) = h;
                *(__half2*)(g_Tl + base + c0) = l;
            }
        }
    }
}

// GEMM2 (batched NT): S[b][i][j] = relu(T[b,i] . H2[b,j] + bias)
__global__ void __launch_bounds__(NTHREADS, 2) gemm2_kernel(
    const float* __restrict__ bias, float* __restrict__ S) {

    const int bat = blockIdx.z;
    const int n1 = g_n1[bat], n2 = g_n2[bat];
    if ((int)blockIdx.y * BM >= n1 || (int)blockIdx.x * BN >= n2) return;

    extern __shared__ char smem[];
    const int tid = threadIdx.x;
    const int cRow = tid >> 1, cCh = tid & 1;

    const int arow = bat * L1S + min((int)blockIdx.y * BM + cRow, n1 - 1);
    const int brow = bat * L2S + min((int)blockIdx.x * BN + cRow, n2 - 1);
    const __half* tAh = g_Th + (size_t)arow * DIM + cCh * 8;
    const __half* tAl = g_Tl + (size_t)arow * DIM + cCh * 8;
    const __half* tBh = g_H2h + (size_t)brow * DIM + cCh * 8;

    float acc[4][4][4];
    gemm_core(tAh, tAl, tBh, acc, smem);

    const int lane = tid & 31, warp = tid >> 5;
    const int g = lane >> 2, t = lane & 3;
    const int gR = blockIdx.y * BM + (warp >> 2) * 64;
    const int gC = blockIdx.x * BN + (warp & 3) * 32;
    const float bb = bias[0];

    #pragma unroll
    for (int mt = 0; mt < 4; mt++) {
        #pragma unroll
        for (int rr = 0; rr < 2; rr++) {
            int r = gR + mt * 16 + g + rr * 8;
            #pragma unroll
            for (int nt = 0; nt < 4; nt++) {
                int c = gC + nt * 8 + t * 2;
                float va = fmaxf(acc[mt][nt][rr * 2 + 0] + bb, 0.0f);
                float vb = fmaxf(acc[mt][nt][rr * 2 + 1] + bb, 0.0f);
                *(float2*)(S + ((size_t)bat * L1S + r) * L2S + c) = make_float2(va, vb);
            }
        }
    }
}

// ------------------------- top-k per batch (compacted region) --------------
#define NB 2048
#define CAP 4096

__global__ void __launch_bounds__(256) topk_kernel(
    const float* __restrict__ S, float* __restrict__ out, int kk) {
    int bat = blockIdx.x;
    const float* Sb = S + (size_t)bat * L1S * L2S;
    const int n1 = g_n1[bat], n2 = g_n2[bat];
    const int span = n1 * L2S;
    const long long nValid = (long long)n1 * n2;

    __shared__ int hist[NB];
    __shared__ float cand[CAP];
    __shared__ int chunkS[128];
    __shared__ int s_cnt, s_cutoff, s_nPos;

    int tid = threadIdx.x;
    for (int i = tid; i < NB; i += 256) hist[i] = 0;
    if (tid == 0) s_cnt = 0;
    __syncthreads();

    for (int t = tid; t < span; t += 256) {
        if ((t & (L2S - 1)) >= n2) continue;
        float f = Sb[t];
        if (f > 0.0f) {
            unsigned u = __float_as_uint(f);
            atomicAdd(&hist[u >> 20], 1);
        }
    }
    __syncthreads();
    if (tid < 128) {
        int s = 0;
        #pragma unroll
        for (int b = 0; b < 16; b++) s += hist[tid * 16 + b];
        chunkS[tid] = s;
    }
    __syncthreads();

    if (tid == 0) {
        int acc = 0, c = -1;
        for (int ch = 127; ch >= 0 && c < 0; ch--) {
            if (acc + chunkS[ch] >= kk) {
                for (int b = ch * 16 + 15; b >= ch * 16; b--) {
                    acc += hist[b];
                    if (acc >= kk) { c = b; break; }
                }
            } else acc += chunkS[ch];
        }
        int totalPos = 0;
        for (int ch = 0; ch < 128; ch++) totalPos += chunkS[ch];
        if (c < 0) c = 0;
        s_cutoff = c;
        s_nPos = totalPos;
    }
    __syncthreads();

    unsigned c = (unsigned)s_cutoff;
    for (int t = tid; t < span; t += 256) {
        if ((t & (L2S - 1)) >= n2) continue;
        float f = Sb[t];
        if (f > 0.0f && (__float_as_uint(f) >> 20) >= c) {
            int idx = atomicAdd(&s_cnt, 1);
            if (idx < CAP) cand[idx] = f;
        }
    }
    __syncthreads();

    int m = min(s_cnt, CAP);
    int P = 2;
    while (P < m) P <<= 1;
    for (int i = m + tid; i < P; i += 256) cand[i] = -1.0f;
    __syncthreads();

    for (int size = 2; size <= P; size <<= 1) {
        for (int stride = size >> 1; stride > 0; stride >>= 1) {
            for (int j = tid; j < P; j += 256) {
                int p = j ^ stride;
                if (p > j) {
                    bool down = ((j & size) == 0);
                    float a = cand[j], b = cand[p];
                    if (down ? (a < b) : (a > b)) { cand[j] = b; cand[p] = a; }
                }
            }
            __syncthreads();
        }
    }

    int nPos = s_nPos;
    int nc = min(min(nPos, m), kk);
    for (int pos = tid; pos < kk; pos += 256) {
        float v;
        if (pos < nc) v = cand[pos];
        else if ((long long)pos < nValid) v = 0.0f;   // remaining valid are relu-zeros
        else v = (nc > 0) ? cand[nc - 1] : 0.0f;      // -inf tail fill
        out[(size_t)bat * kk + pos] = v;
    }
}

// ---------------------------------------------------------------------------
extern "C" void kernel_launch(void* const* d_in, const int* in_sizes, int n_in,
                              void* d_out, int out_size) {
    const float* inputs1 = (const float*)d_in[0];
    const float* inputs2 = (const float*)d_in[1];
    const void*  mask1   = d_in[2];
    const void*  mask2   = d_in[3];
    const float* W       = (const float*)d_in[4];
    const float* bias    = (const float*)d_in[5];
    int kk = out_size / BSZ;   // 256

    float* S;
    cudaGetSymbolAddress((void**)&S, g_S);

    cudaFuncSetAttribute(gemm1_kernel, cudaFuncAttributeMaxDynamicSharedMemorySize, SMEM_DYN);
    cudaFuncSetAttribute(gemm2_kernel, cudaFuncAttributeMaxDynamicSharedMemorySize, SMEM_DYN);

    detect_kernel<<<1, 256>>>((const unsigned long long*)mask1);
    compact_kernel<<<BSZ, 512>>>(mask1, mask2);

    splitA1_kernel<<<MROWS, 256>>>((const float4*)inputs1);
    splitH2_kernel<<<MROWS, 256>>>((const float4*)inputs2);
    splitT_kernel<<<dim3(32, 32), dim3(32, 8)>>>(W);

    dim3 g1(DIM / BN, MROWS / BM);        // (8, 128), CTAs beyond g_nG exit
    gemm1_kernel<<<g1, NTHREADS, SMEM_DYN>>>();

    dim3 g2(L2S / BN, L1S / BM, BSZ);     // (4, 4, 32), CTAs beyond counts exit
    gemm2_kernel<<<g2, NTHREADS, SMEM_DYN>>>(bias, S);

    topk_kernel<<<BSZ, 256>>>(S, (float*)d_out, kk);
}

// round 10
// speedup vs baseline: 3.4278x; 1.1781x over previous
#include <cuda_runtime.h>
#include <cuda_fp16.h>
#include <math_constants.h>
#include <stdint.h>

#define L1S 512
#define L2S 512
#define BSZ 32
#define DIM 1024
#define MROWS (L1S * BSZ)   // 16384

#define BM 128
#define BN 128
#define NTHREADS 256

#define S_STAGES 6
#define ARR_BYTES 6144            // 128 rows * 24 halves * 2B
#define STAGE_BYTES (2 * ARR_BYTES)   // AH, BH
#define AH_OFF 0
#define BH_OFF 6144
#define SMEM_DYN (S_STAGES * STAGE_BYTES)   // 73728

// ------------------------- device global scratch ---------------------------
__device__ __half g_A1h[(size_t)MROWS * DIM];   // global-packed valid rows
__device__ __half g_H2h[(size_t)MROWS * DIM];   // batch-packed valid rows
__device__ __half g_Th [(size_t)MROWS * DIM];   // batch-packed T (fp16)
__device__ __half g_Wh [(size_t)DIM * DIM];     // W^T, fp16
__device__ float g_S[(size_t)BSZ * L1S * L2S];
__device__ int g_is32;
__device__ int g_n1[BSZ];
__device__ int g_n2[BSZ];
__device__ int g_nG;
__device__ int g_idx2[BSZ * L2S];
__device__ int g_gidx[MROWS];   // packed p -> orig flat row (l*BSZ+b)
__device__ int g_gmap[MROWS];   // packed p -> batch-packed T row (b*L1S+pos)

// ------------------------- mask dtype detect (+ counter zero) --------------
__global__ void detect_kernel(const unsigned long long* __restrict__ m1) {
    __shared__ int s;
    if (threadIdx.x == 0) s = 0;
    __syncthreads();
    int bad = 0;
    for (int i = threadIdx.x; i < 8192; i += blockDim.x)
        if (m1[i] > 1ULL) bad = 1;
    if (bad) atomicOr(&s, 1);
    __syncthreads();
    if (threadIdx.x == 0) { g_is32 = s; g_nG = 0; }
    if (threadIdx.x < BSZ) { g_n1[threadIdx.x] = 0; g_n2[threadIdx.x] = 0; }
}

// One block per batch; thread = position. Unordered append (top-k is
// permutation invariant; per-row results are order-independent).
__global__ void __launch_bounds__(512) compact_kernel(
    const void* __restrict__ m1, const void* __restrict__ m2) {
    int b = blockIdx.x, l = threadIdx.x;
    bool is32 = (g_is32 != 0);
    int i = l * BSZ + b;
    long long v1 = is32 ? (long long)((const int*)m1)[i] : ((const long long*)m1)[i];
    long long v2 = is32 ? (long long)((const int*)m2)[i] : ((const long long*)m2)[i];
    if (v1 == 0) {
        int p = atomicAdd(&g_n1[b], 1);
        int q = atomicAdd(&g_nG, 1);
        g_gidx[q] = i;
        g_gmap[q] = b * L1S + p;
    }
    if (v2 == 0) {
        int p = atomicAdd(&g_n2[b], 1);
        g_idx2[b * L2S + p] = l;
    }
}

// Gather inputs1 -> packed fp16 rows.
__global__ void __launch_bounds__(256) splitA1_kernel(const float4* __restrict__ in) {
    int p = blockIdx.x;
    if (p >= g_nG) return;
    int orig = g_gidx[p];
    int t = threadIdx.x;
    float4 v = in[(size_t)orig * (DIM / 4) + t];
    __half2 h0, h1;
    h0.x = __float2half_rn(v.x); h0.y = __float2half_rn(v.y);
    h1.x = __float2half_rn(v.z); h1.y = __float2half_rn(v.w);
    __half2* hp = (__half2*)g_A1h + (size_t)p * (DIM / 2) + t * 2;
    hp[0] = h0; hp[1] = h1;
}

// Gather inputs2 -> batch-packed fp16 rows.
__global__ void __launch_bounds__(256) splitH2_kernel(const float4* __restrict__ in) {
    int p2 = blockIdx.x;
    int bat = p2 >> 9, pos = p2 & (L2S - 1);
    if (pos >= g_n2[bat]) return;
    int l = g_idx2[bat * L2S + pos];
    int t = threadIdx.x;
    float4 v = in[((size_t)l * BSZ + bat) * (DIM / 4) + t];
    __half2 h0, h1;
    h0.x = __float2half_rn(v.x); h0.y = __float2half_rn(v.y);
    h1.x = __float2half_rn(v.z); h1.y = __float2half_rn(v.w);
    __half2* hp = (__half2*)g_H2h + (size_t)p2 * (DIM / 2) + t * 2;
    hp[0] = h0; hp[1] = h1;
}

// transpose W[k][n] -> Wt[n][k], fp16
__global__ void splitT_kernel(const float* __restrict__ W) {
    __shared__ float tile[32][33];
    int k0 = blockIdx.y * 32, n0 = blockIdx.x * 32;
    for (int r = threadIdx.y; r < 32; r += 8)
        tile[r][threadIdx.x] = W[(size_t)(k0 + r) * DIM + n0 + threadIdx.x];
    __syncthreads();
    for (int r = threadIdx.y; r < 32; r += 8)
        g_Wh[(size_t)(n0 + r) * DIM + k0 + threadIdx.x] =
            __float2half_rn(tile[threadIdx.x][r]);
}

// ------------------------- tensor-core GEMM core ---------------------------
__device__ __forceinline__ void cp16s(unsigned d, const void* src) {
    asm volatile("cp.async.cg.shared.global [%0], [%1], 16;\n" :: "r"(d), "l"(src));
}
__device__ __forceinline__ void ldm4(unsigned& r0, unsigned& r1, unsigned& r2,
                                     unsigned& r3, unsigned a) {
    asm volatile("ldmatrix.sync.aligned.m8n8.x4.shared.b16 {%0,%1,%2,%3}, [%4];\n"
                 : "=r"(r0), "=r"(r1), "=r"(r2), "=r"(r3) : "r"(a));
}
__device__ __forceinline__ void mma16816(float* c, const unsigned* a, const unsigned* b) {
    asm volatile(
        "mma.sync.aligned.m16n8k16.row.col.f32.f16.f16.f32 "
        "{%0,%1,%2,%3}, {%4,%5,%6,%7}, {%8,%9}, {%0,%1,%2,%3};\n"
        : "+f"(c[0]), "+f"(c[1]), "+f"(c[2]), "+f"(c[3])
        : "r"(a[0]), "r"(a[1]), "r"(a[2]), "r"(a[3]), "r"(b[0]), "r"(b[1]));
}

// C[BM,BN] += A[BM,K] * B[BN,K]^T, single fp16, fp32 accum.
// 8 warps = 2(m) x 4(n); warp tile 64x32. 6-stage cp.async pipeline + ldmatrix.
__device__ __forceinline__ void gemm_core(
    const __half* __restrict__ tAh, const __half* __restrict__ tBh,
    float acc[4][4][4], char* smem) {

    const int tid = threadIdx.x;
    const int lane = tid & 31, warp = tid >> 5;
    const int WR = (warp >> 2) * 64, WC = (warp & 3) * 32;
    const unsigned sbase = (unsigned)__cvta_generic_to_shared(smem);

    const unsigned cByte = (unsigned)((tid >> 1) * 48 + (tid & 1) * 16);

    const int tle = lane >> 3, lr = lane & 7;
    const unsigned aByte = (unsigned)(((WR + (tle & 1) * 8 + lr) * 24 + (tle >> 1) * 8) * 2);
    const unsigned bByte = (unsigned)(((WC + (tle >> 1) * 8 + lr) * 24 + (tle & 1) * 8) * 2);

    #pragma unroll
    for (int a = 0; a < 4; a++)
        #pragma unroll
        for (int b = 0; b < 4; b++)
            #pragma unroll
            for (int c = 0; c < 4; c++) acc[a][b][c] = 0.0f;

    auto issue = [&](int kt, int stage) {
        unsigned so = sbase + stage * STAGE_BYTES + cByte;
        cp16s(so + AH_OFF, tAh + kt);
        cp16s(so + BH_OFF, tBh + kt);
        asm volatile("cp.async.commit_group;\n" ::);
    };

    const int NK = DIM >> 4;   // 64
    #pragma unroll
    for (int s = 0; s < S_STAGES - 1; s++) issue(s << 4, s);

    int stage = 0, wstage = S_STAGES - 1;
    for (int i = 0; i < NK; i++) {
        asm volatile("cp.async.wait_group %0;\n" :: "n"(S_STAGES - 2));
        __syncthreads();

        const unsigned st = sbase + stage * STAGE_BYTES;

        unsigned bh[4][2];
        ldm4(bh[0][0], bh[0][1], bh[1][0], bh[1][1], st + BH_OFF + bByte);
        ldm4(bh[2][0], bh[2][1], bh[3][0], bh[3][1], st + BH_OFF + bByte + 768);

        #pragma unroll
        for (int mt = 0; mt < 4; mt++) {
            unsigned ah[4];
            ldm4(ah[0], ah[1], ah[2], ah[3], st + AH_OFF + aByte + mt * 768);
            #pragma unroll
            for (int nt = 0; nt < 4; nt++)
                mma16816(acc[mt][nt], ah, bh[nt]);
        }

        int nxt = i + S_STAGES - 1;
        if (nxt < NK) {
            issue(nxt << 4, wstage);
        } else {
            asm volatile("cp.async.commit_group;\n" ::);
        }
        if (++stage == S_STAGES) stage = 0;
        if (++wstage == S_STAGES) wstage = 0;
    }
}

// GEMM1: T[gmap[p]] = A1packed[p] * Wt^T  (fp16 out)
__global__ void __launch_bounds__(NTHREADS, 2) gemm1_kernel() {
    const int ng = g_nG;
    if ((int)blockIdx.y * BM >= ng) return;

    extern __shared__ char smem[];
    const int tid = threadIdx.x;
    const int cRow = tid >> 1, cCh = tid & 1;

    const int ar = min((int)blockIdx.y * BM + cRow, ng - 1);
    const __half* tAh = g_A1h + (size_t)ar * DIM + cCh * 8;
    const __half* tBh = g_Wh + (size_t)(blockIdx.x * BN + cRow) * DIM + cCh * 8;

    float acc[4][4][4];
    gemm_core(tAh, tBh, acc, smem);

    const int lane = tid & 31, warp = tid >> 5;
    const int g = lane >> 2, t = lane & 3;
    const int pR = blockIdx.y * BM + (warp >> 2) * 64;
    const int gC = blockIdx.x * BN + (warp & 3) * 32;

    #pragma unroll
    for (int mt = 0; mt < 4; mt++) {
        #pragma unroll
        for (int rr = 0; rr < 2; rr++) {
            int p = pR + mt * 16 + g + rr * 8;
            if (p >= ng) continue;
            size_t base = (size_t)g_gmap[p] * DIM;
            #pragma unroll
            for (int nt = 0; nt < 4; nt++) {
                int c0 = gC + nt * 8 + t * 2;
                __half2 h;
                h.x = __float2half_rn(acc[mt][nt][rr * 2 + 0]);
                h.y = __float2half_rn(acc[mt][nt][rr * 2 + 1]);
                *(__half2*)(g_Th + base + c0) = h;
            }
        }
    }
}

// GEMM2 (batched NT): S[b][i][j] = relu(T[b,i] . H2[b,j] + bias)
__global__ void __launch_bounds__(NTHREADS, 2) gemm2_kernel(
    const float* __restrict__ bias, float* __restrict__ S) {

    const int bat = blockIdx.z;
    const int n1 = g_n1[bat], n2 = g_n2[bat];
    if ((int)blockIdx.y * BM >= n1 || (int)blockIdx.x * BN >= n2) return;

    extern __shared__ char smem[];
    const int tid = threadIdx.x;
    const int cRow = tid >> 1, cCh = tid & 1;

    const int arow = bat * L1S + min((int)blockIdx.y * BM + cRow, n1 - 1);
    const int brow = bat * L2S + min((int)blockIdx.x * BN + cRow, n2 - 1);
    const __half* tAh = g_Th + (size_t)arow * DIM + cCh * 8;
    const __half* tBh = g_H2h + (size_t)brow * DIM + cCh * 8;

    float acc[4][4][4];
    gemm_core(tAh, tBh, acc, smem);

    const int lane = tid & 31, warp = tid >> 5;
    const int g = lane >> 2, t = lane & 3;
    const int gR = blockIdx.y * BM + (warp >> 2) * 64;
    const int gC = blockIdx.x * BN + (warp & 3) * 32;
    const float bb = bias[0];

    #pragma unroll
    for (int mt = 0; mt < 4; mt++) {
        #pragma unroll
        for (int rr = 0; rr < 2; rr++) {
            int r = gR + mt * 16 + g + rr * 8;
            #pragma unroll
            for (int nt = 0; nt < 4; nt++) {
                int c = gC + nt * 8 + t * 2;
                float va = fmaxf(acc[mt][nt][rr * 2 + 0] + bb, 0.0f);
                float vb = fmaxf(acc[mt][nt][rr * 2 + 1] + bb, 0.0f);
                *(float2*)(S + ((size_t)bat * L1S + r) * L2S + c) = make_float2(va, vb);
            }
        }
    }
}

// ------------------------- top-k per batch (compacted region) --------------
#define NB 2048
#define CAP 4096

__global__ void __launch_bounds__(256) topk_kernel(
    const float* __restrict__ S, float* __restrict__ out, int kk) {
    int bat = blockIdx.x;
    const float* Sb = S + (size_t)bat * L1S * L2S;
    const int n1 = g_n1[bat], n2 = g_n2[bat];
    const int span = n1 * L2S;
    const long long nValid = (long long)n1 * n2;

    __shared__ int hist[NB];
    __shared__ float cand[CAP];
    __shared__ int chunkS[128];
    __shared__ int s_cnt, s_cutoff, s_nPos;

    int tid = threadIdx.x;
    for (int i = tid; i < NB; i += 256) hist[i] = 0;
    if (tid == 0) s_cnt = 0;
    __syncthreads();

    for (int t = tid; t < span; t += 256) {
        if ((t & (L2S - 1)) >= n2) continue;
        float f = Sb[t];
        if (f > 0.0f) {
            unsigned u = __float_as_uint(f);
            atomicAdd(&hist[u >> 20], 1);
        }
    }
    __syncthreads();
    if (tid < 128) {
        int s = 0;
        #pragma unroll
        for (int b = 0; b < 16; b++) s += hist[tid * 16 + b];
        chunkS[tid] = s;
    }
    __syncthreads();

    if (tid == 0) {
        int acc = 0, c = -1;
        for (int ch = 127; ch >= 0 && c < 0; ch--) {
            if (acc + chunkS[ch] >= kk) {
                for (int b = ch * 16 + 15; b >= ch * 16; b--) {
                    acc += hist[b];
                    if (acc >= kk) { c = b; break; }
                }
            } else acc += chunkS[ch];
        }
        int totalPos = 0;
        for (int ch = 0; ch < 128; ch++) totalPos += chunkS[ch];
        if (c < 0) c = 0;
        s_cutoff = c;
        s_nPos = totalPos;
    }
    __syncthreads();

    unsigned c = (unsigned)s_cutoff;
    for (int t = tid; t < span; t += 256) {
        if ((t & (L2S - 1)) >= n2) continue;
        float f = Sb[t];
        if (f > 0.0f && (__float_as_uint(f) >> 20) >= c) {
            int idx = atomicAdd(&s_cnt, 1);
            if (idx < CAP) cand[idx] = f;
        }
    }
    __syncthreads();

    int m = min(s_cnt, CAP);
    int P = 2;
    while (P < m) P <<= 1;
    for (int i = m + tid; i < P; i += 256) cand[i] = -1.0f;
    __syncthreads();

    for (int size = 2; size <= P; size <<= 1) {
        for (int stride = size >> 1; stride > 0; stride >>= 1) {
            for (int j = tid; j < P; j += 256) {
                int p = j ^ stride;
                if (p > j) {
                    bool down = ((j & size) == 0);
                    float a = cand[j], b = cand[p];
                    if (down ? (a < b) : (a > b)) { cand[j] = b; cand[p] = a; }
                }
            }
            __syncthreads();
        }
    }

    int nPos = s_nPos;
    int nc = min(min(nPos, m), kk);
    for (int pos = tid; pos < kk; pos += 256) {
        float v;
        if (pos < nc) v = cand[pos];
        else if ((long long)pos < nValid) v = 0.0f;   // remaining valid are relu-zeros
        else v = (nc > 0) ? cand[nc - 1] : 0.0f;      // -inf tail fill
        out[(size_t)bat * kk + pos] = v;
    }
}

// ---------------------------------------------------------------------------
extern "C" void kernel_launch(void* const* d_in, const int* in_sizes, int n_in,
                              void* d_out, int out_size) {
    const float* inputs1 = (const float*)d_in[0];
    const float* inputs2 = (const float*)d_in[1];
    const void*  mask1   = d_in[2];
    const void*  mask2   = d_in[3];
    const float* W       = (const float*)d_in[4];
    const float* bias    = (const float*)d_in[5];
    int kk = out_size / BSZ;   // 256

    float* S;
    cudaGetSymbolAddress((void**)&S, g_S);

    cudaFuncSetAttribute(gemm1_kernel, cudaFuncAttributeMaxDynamicSharedMemorySize, SMEM_DYN);
    cudaFuncSetAttribute(gemm2_kernel, cudaFuncAttributeMaxDynamicSharedMemorySize, SMEM_DYN);

    detect_kernel<<<1, 256>>>((const unsigned long long*)mask1);
    compact_kernel<<<BSZ, 512>>>(mask1, mask2);

    splitA1_kernel<<<MROWS, 256>>>((const float4*)inputs1);
    splitH2_kernel<<<MROWS, 256>>>((const float4*)inputs2);
    splitT_kernel<<<dim3(32, 32), dim3(32, 8)>>>(W);

    dim3 g1(DIM / BN, MROWS / BM);        // (8, 128), CTAs beyond g_nG exit
    gemm1_kernel<<<g1, NTHREADS, SMEM_DYN>>>();

    dim3 g2(L2S / BN, L1S / BM, BSZ);     // (4, 4, 32), CTAs beyond counts exit
    gemm2_kernel<<<g2, NTHREADS, SMEM_DYN>>>(bias, S);

    topk_kernel<<<BSZ, 256>>>(S, (float*)d_out, kk);
}